// round 2
// baseline (speedup 1.0000x reference)
#include <cuda_runtime.h>
#include <math.h>

// ---------------------------------------------------------------------------
// Problem constants: x [4,2048,1024], 16 heads, head_dim 64.
// ---------------------------------------------------------------------------
#define BATCH 4
#define SEQ   2048
#define DM    1024
#define NH    16
#define HD    64
#define MROWS (BATCH * SEQ)   // 8192

// Scratch (device globals: allocation-free per harness rules)
__device__ float g_q[BATCH * NH * SEQ * HD];
__device__ float g_k[BATCH * NH * SEQ * HD];
__device__ float g_v[BATCH * NH * SEQ * HD];
__device__ float g_ctx[MROWS * DM];

// ---------------------------------------------------------------------------
// GEMM with bias: C = (A[M,1024] @ B[1024,1024] + bias) * scale
// qkv!=0: scatter output to [b, h, s, hd] layout; else plain row-major.
// BM=BN=128, BK=16, 256 threads, 8x8 register tile.
// ---------------------------------------------------------------------------
__global__ __launch_bounds__(256) void gemm_bias(
    const float* __restrict__ A, const float* __restrict__ B,
    const float* __restrict__ bias, float* __restrict__ C,
    int qkv, float scale)
{
    __shared__ float As[16][132];   // transposed A tile, padded
    __shared__ float Bs[16][128];

    const int tid     = threadIdx.x;
    const int rowBase = blockIdx.y * 128;
    const int colBase = blockIdx.x * 128;
    const int tRow    = (tid >> 4) * 8;
    const int tCol    = (tid & 15) * 8;

    float acc[8][8];
#pragma unroll
    for (int i = 0; i < 8; i++)
#pragma unroll
        for (int j = 0; j < 8; j++) acc[i][j] = 0.f;

    for (int k0 = 0; k0 < DM; k0 += 16) {
        // Load A tile (128 rows x 16 cols), store transposed
#pragma unroll
        for (int it = 0; it < 2; it++) {
            int idx = tid + it * 256;          // 0..511
            int r   = idx >> 2;                // 0..127
            int c4  = (idx & 3) * 4;           // 0,4,8,12
            float4 v = *(const float4*)(A + (size_t)(rowBase + r) * DM + k0 + c4);
            As[c4 + 0][r] = v.x; As[c4 + 1][r] = v.y;
            As[c4 + 2][r] = v.z; As[c4 + 3][r] = v.w;
        }
        // Load B tile (16 rows x 128 cols)
#pragma unroll
        for (int it = 0; it < 2; it++) {
            int idx = tid + it * 256;
            int r   = idx >> 5;                // 0..15
            int c4  = (idx & 31) * 4;          // 0..124
            *(float4*)&Bs[r][c4] =
                *(const float4*)(B + (size_t)(k0 + r) * DM + colBase + c4);
        }
        __syncthreads();

#pragma unroll
        for (int k = 0; k < 16; k++) {
            float4 a0 = *(const float4*)&As[k][tRow];
            float4 a1 = *(const float4*)&As[k][tRow + 4];
            float4 b0 = *(const float4*)&Bs[k][tCol];
            float4 b1 = *(const float4*)&Bs[k][tCol + 4];
            float ar[8] = {a0.x, a0.y, a0.z, a0.w, a1.x, a1.y, a1.z, a1.w};
            float br[8] = {b0.x, b0.y, b0.z, b0.w, b1.x, b1.y, b1.z, b1.w};
#pragma unroll
            for (int i = 0; i < 8; i++)
#pragma unroll
                for (int j = 0; j < 8; j++)
                    acc[i][j] = fmaf(ar[i], br[j], acc[i][j]);
        }
        __syncthreads();
    }

    float bb[8];
#pragma unroll
    for (int j = 0; j < 8; j++) bb[j] = bias[colBase + tCol + j];

    if (!qkv) {
#pragma unroll
        for (int i = 0; i < 8; i++) {
            int row = rowBase + tRow + i;
            float4 o0, o1;
            o0.x = (acc[i][0] + bb[0]) * scale; o0.y = (acc[i][1] + bb[1]) * scale;
            o0.z = (acc[i][2] + bb[2]) * scale; o0.w = (acc[i][3] + bb[3]) * scale;
            o1.x = (acc[i][4] + bb[4]) * scale; o1.y = (acc[i][5] + bb[5]) * scale;
            o1.z = (acc[i][6] + bb[6]) * scale; o1.w = (acc[i][7] + bb[7]) * scale;
            *(float4*)(C + (size_t)row * DM + colBase + tCol)     = o0;
            *(float4*)(C + (size_t)row * DM + colBase + tCol + 4) = o1;
        }
    } else {
        // scatter to [b, h, s, hd]
#pragma unroll
        for (int i = 0; i < 8; i++) {
            int row = rowBase + tRow + i;
            int b = row >> 11;          // /2048
            int s = row & 2047;
#pragma unroll
            for (int j = 0; j < 8; j++) {
                int n  = colBase + tCol + j;
                int h  = n >> 6;
                int hd = n & 63;
                C[(((size_t)(b * NH + h) * SEQ) + s) * HD + hd] =
                    (acc[i][j] + bb[j]) * scale;
            }
        }
    }
}

// ---------------------------------------------------------------------------
// Flash attention, fp32, causal. Q pre-scaled by 1/sqrt(HD).
// Q,K,V: [b*h][2048][64]; ctx out: [b*2048][1024] (head-interleaved columns).
// Block: 256 threads handles one 64-query tile; loops kt = 0..qt.
// ---------------------------------------------------------------------------
__global__ __launch_bounds__(256) void flash_attn(
    const float* __restrict__ Q, const float* __restrict__ K,
    const float* __restrict__ V, float* __restrict__ ctx)
{
    __shared__ float Qts[64][64];   // [d][q]  (transposed)
    __shared__ float KPs[64][64];   // phase 1: K^T [d][k]; phase 2: P [q][k]
    __shared__ float Vs[64][64];    // [k][d]

    const int tid = threadIdx.x;
    const int qt  = blockIdx.x;
    const int bh  = blockIdx.y;
    const int ty  = tid >> 4, tx = tid & 15;
    const int r0  = ty * 4,  c0 = tx * 4;

    const size_t base = (size_t)bh * SEQ * HD;

    // Load Q tile transposed (conflict-free smem writes)
    {
        const float* Qb = Q + base + (size_t)qt * 64 * HD;
#pragma unroll
        for (int it = 0; it < 4; it++) {
            int idx = tid + it * 256;        // 0..1023
            int r   = idx & 63;              // query row
            int c4  = (idx >> 6) * 4;        // d
            float4 v = *(const float4*)(Qb + r * HD + c4);
            Qts[c4 + 0][r] = v.x; Qts[c4 + 1][r] = v.y;
            Qts[c4 + 2][r] = v.z; Qts[c4 + 3][r] = v.w;
        }
    }

    float m[4], l[4], O[4][4];
#pragma unroll
    for (int i = 0; i < 4; i++) {
        m[i] = -INFINITY; l[i] = 0.f;
#pragma unroll
        for (int j = 0; j < 4; j++) O[i][j] = 0.f;
    }
    __syncthreads();

    for (int kt = 0; kt <= qt; kt++) {
        const float* Kb = K + base + (size_t)kt * 64 * HD;
        const float* Vb = V + base + (size_t)kt * 64 * HD;
#pragma unroll
        for (int it = 0; it < 4; it++) {
            int idx = tid + it * 256;
            int r   = idx & 63;
            int c4  = (idx >> 6) * 4;
            float4 kv = *(const float4*)(Kb + r * HD + c4);
            KPs[c4 + 0][r] = kv.x; KPs[c4 + 1][r] = kv.y;
            KPs[c4 + 2][r] = kv.z; KPs[c4 + 3][r] = kv.w;
        }
#pragma unroll
        for (int it = 0; it < 4; it++) {
            int idx = tid + it * 256;
            int r   = idx >> 4;              // 0..63
            int c4  = (idx & 15) * 4;
            *(float4*)&Vs[r][c4] = *(const float4*)(Vb + r * HD + c4);
        }
        __syncthreads();

        // S = Q K^T  (4x4 per thread)
        float S[4][4];
#pragma unroll
        for (int i = 0; i < 4; i++)
#pragma unroll
            for (int j = 0; j < 4; j++) S[i][j] = 0.f;

#pragma unroll
        for (int d = 0; d < 64; d++) {
            float4 qq = *(const float4*)&Qts[d][r0];
            float4 kk = *(const float4*)&KPs[d][c0];
            float qa[4] = {qq.x, qq.y, qq.z, qq.w};
            float ka[4] = {kk.x, kk.y, kk.z, kk.w};
#pragma unroll
            for (int i = 0; i < 4; i++)
#pragma unroll
                for (int j = 0; j < 4; j++)
                    S[i][j] = fmaf(qa[i], ka[j], S[i][j]);
        }

        if (kt == qt) {   // causal mask inside diagonal tile
#pragma unroll
            for (int i = 0; i < 4; i++)
#pragma unroll
                for (int j = 0; j < 4; j++)
                    if (c0 + j > r0 + i) S[i][j] = -INFINITY;
        }

        // online softmax update
#pragma unroll
        for (int i = 0; i < 4; i++) {
            float tm = fmaxf(fmaxf(S[i][0], S[i][1]), fmaxf(S[i][2], S[i][3]));
#pragma unroll
            for (int off = 8; off; off >>= 1)
                tm = fmaxf(tm, __shfl_xor_sync(0xffffffffu, tm, off));
            float mn = fmaxf(m[i], tm);
            float sc = __expf(m[i] - mn);
            m[i] = mn;
#pragma unroll
            for (int j = 0; j < 4; j++) S[i][j] = __expf(S[i][j] - mn);
            float rs = S[i][0] + S[i][1] + S[i][2] + S[i][3];
#pragma unroll
            for (int off = 8; off; off >>= 1)
                rs += __shfl_xor_sync(0xffffffffu, rs, off);
            l[i] = l[i] * sc + rs;
#pragma unroll
            for (int j = 0; j < 4; j++) O[i][j] *= sc;
        }

        __syncthreads();   // everyone done reading K^T
        // write P into KPs as [q][k]
#pragma unroll
        for (int i = 0; i < 4; i++)
            *(float4*)&KPs[r0 + i][c0] = make_float4(S[i][0], S[i][1], S[i][2], S[i][3]);
        __syncthreads();

        // O += P @ V
#pragma unroll
        for (int k = 0; k < 64; k++) {
            float4 vv = *(const float4*)&Vs[k][c0];
            float va[4] = {vv.x, vv.y, vv.z, vv.w};
            float p0 = KPs[r0 + 0][k], p1 = KPs[r0 + 1][k];
            float p2 = KPs[r0 + 2][k], p3 = KPs[r0 + 3][k];
#pragma unroll
            for (int j = 0; j < 4; j++) {
                O[0][j] = fmaf(p0, va[j], O[0][j]);
                O[1][j] = fmaf(p1, va[j], O[1][j]);
                O[2][j] = fmaf(p2, va[j], O[2][j]);
                O[3][j] = fmaf(p3, va[j], O[3][j]);
            }
        }
        __syncthreads();   // before next iteration overwrites KPs / Vs
    }

    // epilogue: normalize and write ctx [b*2048 + q][h*64 + hd]
    const int b = bh >> 4, h = bh & 15;
#pragma unroll
    for (int i = 0; i < 4; i++) {
        float inv = 1.f / l[i];
        int q = qt * 64 + r0 + i;
        float4 o = make_float4(O[i][0] * inv, O[i][1] * inv,
                               O[i][2] * inv, O[i][3] * inv);
        *(float4*)(ctx + ((size_t)(b * SEQ + q)) * DM + h * HD + c0) = o;
    }
}

// ---------------------------------------------------------------------------
// Launch
// ---------------------------------------------------------------------------
extern "C" void kernel_launch(void* const* d_in, const int* in_sizes, int n_in,
                              void* d_out, int out_size)
{
    const float* x  = (const float*)d_in[0];
    const float* wq = (const float*)d_in[1];
    const float* bq = (const float*)d_in[2];
    const float* wk = (const float*)d_in[3];
    const float* bk = (const float*)d_in[4];
    const float* wv = (const float*)d_in[5];
    const float* bv = (const float*)d_in[6];
    const float* wo = (const float*)d_in[7];
    const float* bo = (const float*)d_in[8];
    float* out = (float*)d_out;

    float *q, *k, *v, *ctx;
    cudaGetSymbolAddress((void**)&q,   g_q);
    cudaGetSymbolAddress((void**)&k,   g_k);
    cudaGetSymbolAddress((void**)&v,   g_v);
    cudaGetSymbolAddress((void**)&ctx, g_ctx);

    dim3 gg(DM / 128, MROWS / 128);   // (8, 64)
    const float qscale = 0.125f;      // 1/sqrt(64)

    gemm_bias<<<gg, 256>>>(x, wq, bq, q, 1, qscale);
    gemm_bias<<<gg, 256>>>(x, wk, bk, k, 1, 1.0f);
    gemm_bias<<<gg, 256>>>(x, wv, bv, v, 1, 1.0f);

    flash_attn<<<dim3(SEQ / 64, BATCH * NH), 256>>>(q, k, v, ctx);

    gemm_bias<<<gg, 256>>>(ctx, wo, bo, out, 0, 1.0f);
}

// round 3
// speedup vs baseline: 1.5911x; 1.5911x over previous
#include <cuda_runtime.h>
#include <math.h>

#define BATCH 4
#define SEQ   2048
#define DM    1024
#define NH    16
#define HD    64
#define MROWS (BATCH * SEQ)   // 8192

__device__ float g_q[BATCH * NH * SEQ * HD];
__device__ float g_k[BATCH * NH * SEQ * HD];
__device__ float g_v[BATCH * NH * SEQ * HD];
__device__ float g_ctx[MROWS * DM];

// ---------------------------------------------------------------------------
// tf32 helpers
// ---------------------------------------------------------------------------
__device__ __forceinline__ unsigned f2tf32(float f) {
    unsigned u;
    asm("cvt.rna.tf32.f32 %0, %1;" : "=r"(u) : "f"(f));
    return u;
}

__device__ __forceinline__ void mma_tf32(float* d, const unsigned* a,
                                         unsigned b0, unsigned b1) {
    asm volatile(
        "mma.sync.aligned.m16n8k8.row.col.f32.tf32.tf32.f32 "
        "{%0,%1,%2,%3}, {%4,%5,%6,%7}, {%8,%9}, {%0,%1,%2,%3};\n"
        : "+f"(d[0]), "+f"(d[1]), "+f"(d[2]), "+f"(d[3])
        : "r"(a[0]), "r"(a[1]), "r"(a[2]), "r"(a[3]), "r"(b0), "r"(b1));
}

// ---------------------------------------------------------------------------
// tf32 tensor-core GEMM: C = (A[M,1024] @ B[1024,1024] + bias) * scale
// qkv!=0: scatter to [b, h, s, hd]; else plain row-major.
// BM=BN=128, BK=32, 256 threads (8 warps, 4x2), warp tile 32x64.
// ---------------------------------------------------------------------------
__global__ __launch_bounds__(256) void gemm_tf32(
    const float* __restrict__ A, const float* __restrict__ B,
    const float* __restrict__ bias, float* __restrict__ C,
    int qkv, float scale)
{
    __shared__ unsigned As[128][36];   // [m][k], row pad -> (4m+k)%32 distinct
    __shared__ unsigned Bs[32][132];   // [k][n]

    const int tid   = threadIdx.x;
    const int lane  = tid & 31;
    const int warp  = tid >> 5;
    const int warpM = warp & 3;        // 0..3, 32 rows each
    const int warpN = warp >> 2;       // 0..1, 64 cols each
    const int g     = lane >> 2;       // 0..7
    const int t     = lane & 3;        // 0..3
    const int rowBase = blockIdx.y * 128;
    const int colBase = blockIdx.x * 128;

    float d[2][8][4];
#pragma unroll
    for (int mt = 0; mt < 2; mt++)
#pragma unroll
        for (int nt = 0; nt < 8; nt++)
#pragma unroll
            for (int j = 0; j < 4; j++) d[mt][nt][j] = 0.f;

    for (int k0 = 0; k0 < DM; k0 += 32) {
        // A tile: 128 rows x 32 k, row-major, cvt -> tf32
#pragma unroll
        for (int it = 0; it < 4; it++) {
            int linear = tid + it * 256;     // 0..1023
            int r  = linear >> 3;            // 0..127
            int c4 = (linear & 7) * 4;       // 0..28
            float4 v = *(const float4*)(A + (size_t)(rowBase + r) * DM + k0 + c4);
            uint4 u = make_uint4(f2tf32(v.x), f2tf32(v.y), f2tf32(v.z), f2tf32(v.w));
            *(uint4*)&As[r][c4] = u;
        }
        // B tile: 32 k x 128 n
#pragma unroll
        for (int it = 0; it < 4; it++) {
            int linear = tid + it * 256;
            int r  = linear >> 5;            // 0..31
            int c4 = (linear & 31) * 4;      // 0..124
            float4 v = *(const float4*)(B + (size_t)(k0 + r) * DM + colBase + c4);
            uint4 u = make_uint4(f2tf32(v.x), f2tf32(v.y), f2tf32(v.z), f2tf32(v.w));
            *(uint4*)&Bs[r][c4] = u;
        }
        __syncthreads();

#pragma unroll
        for (int kk = 0; kk < 32; kk += 8) {
            unsigned a[2][4];
#pragma unroll
            for (int mt = 0; mt < 2; mt++) {
                int rb = warpM * 32 + mt * 16;
                a[mt][0] = As[rb + g    ][kk + t];
                a[mt][1] = As[rb + g + 8][kk + t];
                a[mt][2] = As[rb + g    ][kk + t + 4];
                a[mt][3] = As[rb + g + 8][kk + t + 4];
            }
#pragma unroll
            for (int nt = 0; nt < 8; nt++) {
                int cb = warpN * 64 + nt * 8;
                unsigned b0 = Bs[kk + t    ][cb + g];
                unsigned b1 = Bs[kk + t + 4][cb + g];
                mma_tf32(d[0][nt], a[0], b0, b1);
                mma_tf32(d[1][nt], a[1], b0, b1);
            }
        }
        __syncthreads();
    }

    // epilogue
#pragma unroll
    for (int mt = 0; mt < 2; mt++) {
        int row0 = rowBase + warpM * 32 + mt * 16 + g;
#pragma unroll
        for (int nt = 0; nt < 8; nt++) {
            int col = colBase + warpN * 64 + nt * 8 + 2 * t;
            float bb0 = bias[col], bb1 = bias[col + 1];
            float v00 = (d[mt][nt][0] + bb0) * scale;
            float v01 = (d[mt][nt][1] + bb1) * scale;
            float v10 = (d[mt][nt][2] + bb0) * scale;
            float v11 = (d[mt][nt][3] + bb1) * scale;
            if (!qkv) {
                *(float2*)(C + (size_t)row0 * DM + col)       = make_float2(v00, v01);
                *(float2*)(C + (size_t)(row0 + 8) * DM + col) = make_float2(v10, v11);
            } else {
                int h = col >> 6, hd = col & 63;
                int b0i = row0 >> 11, s0 = row0 & 2047;
                int r1 = row0 + 8;
                int b1i = r1 >> 11, s1 = r1 & 2047;
                size_t base0 = (((size_t)(b0i * NH + h) * SEQ) + s0) * HD + hd;
                size_t base1 = (((size_t)(b1i * NH + h) * SEQ) + s1) * HD + hd;
                C[base0]     = v00;
                C[base0 + 1] = v01;
                C[base1]     = v10;
                C[base1 + 1] = v11;
            }
        }
    }
}

// ---------------------------------------------------------------------------
// Flash attention, fp32, causal (unchanged from R1). Q pre-scaled 1/sqrt(HD).
// ---------------------------------------------------------------------------
__global__ __launch_bounds__(256) void flash_attn(
    const float* __restrict__ Q, const float* __restrict__ K,
    const float* __restrict__ V, float* __restrict__ ctx)
{
    __shared__ float Qts[64][64];
    __shared__ float KPs[64][64];
    __shared__ float Vs[64][64];

    const int tid = threadIdx.x;
    const int qt  = blockIdx.x;
    const int bh  = blockIdx.y;
    const int ty  = tid >> 4, tx = tid & 15;
    const int r0  = ty * 4,  c0 = tx * 4;

    const size_t base = (size_t)bh * SEQ * HD;

    {
        const float* Qb = Q + base + (size_t)qt * 64 * HD;
#pragma unroll
        for (int it = 0; it < 4; it++) {
            int idx = tid + it * 256;
            int r   = idx & 63;
            int c4  = (idx >> 6) * 4;
            float4 v = *(const float4*)(Qb + r * HD + c4);
            Qts[c4 + 0][r] = v.x; Qts[c4 + 1][r] = v.y;
            Qts[c4 + 2][r] = v.z; Qts[c4 + 3][r] = v.w;
        }
    }

    float m[4], l[4], O[4][4];
#pragma unroll
    for (int i = 0; i < 4; i++) {
        m[i] = -INFINITY; l[i] = 0.f;
#pragma unroll
        for (int j = 0; j < 4; j++) O[i][j] = 0.f;
    }
    __syncthreads();

    for (int kt = 0; kt <= qt; kt++) {
        const float* Kb = K + base + (size_t)kt * 64 * HD;
        const float* Vb = V + base + (size_t)kt * 64 * HD;
#pragma unroll
        for (int it = 0; it < 4; it++) {
            int idx = tid + it * 256;
            int r   = idx & 63;
            int c4  = (idx >> 6) * 4;
            float4 kv = *(const float4*)(Kb + r * HD + c4);
            KPs[c4 + 0][r] = kv.x; KPs[c4 + 1][r] = kv.y;
            KPs[c4 + 2][r] = kv.z; KPs[c4 + 3][r] = kv.w;
        }
#pragma unroll
        for (int it = 0; it < 4; it++) {
            int idx = tid + it * 256;
            int r   = idx >> 4;
            int c4  = (idx & 15) * 4;
            *(float4*)&Vs[r][c4] = *(const float4*)(Vb + r * HD + c4);
        }
        __syncthreads();

        float S[4][4];
#pragma unroll
        for (int i = 0; i < 4; i++)
#pragma unroll
            for (int j = 0; j < 4; j++) S[i][j] = 0.f;

#pragma unroll
        for (int dd = 0; dd < 64; dd++) {
            float4 qq = *(const float4*)&Qts[dd][r0];
            float4 kk = *(const float4*)&KPs[dd][c0];
            float qa[4] = {qq.x, qq.y, qq.z, qq.w};
            float ka[4] = {kk.x, kk.y, kk.z, kk.w};
#pragma unroll
            for (int i = 0; i < 4; i++)
#pragma unroll
                for (int j = 0; j < 4; j++)
                    S[i][j] = fmaf(qa[i], ka[j], S[i][j]);
        }

        if (kt == qt) {
#pragma unroll
            for (int i = 0; i < 4; i++)
#pragma unroll
                for (int j = 0; j < 4; j++)
                    if (c0 + j > r0 + i) S[i][j] = -INFINITY;
        }

#pragma unroll
        for (int i = 0; i < 4; i++) {
            float tm = fmaxf(fmaxf(S[i][0], S[i][1]), fmaxf(S[i][2], S[i][3]));
#pragma unroll
            for (int off = 8; off; off >>= 1)
                tm = fmaxf(tm, __shfl_xor_sync(0xffffffffu, tm, off));
            float mn = fmaxf(m[i], tm);
            float sc = __expf(m[i] - mn);
            m[i] = mn;
#pragma unroll
            for (int j = 0; j < 4; j++) S[i][j] = __expf(S[i][j] - mn);
            float rs = S[i][0] + S[i][1] + S[i][2] + S[i][3];
#pragma unroll
            for (int off = 8; off; off >>= 1)
                rs += __shfl_xor_sync(0xffffffffu, rs, off);
            l[i] = l[i] * sc + rs;
#pragma unroll
            for (int j = 0; j < 4; j++) O[i][j] *= sc;
        }

        __syncthreads();
#pragma unroll
        for (int i = 0; i < 4; i++)
            *(float4*)&KPs[r0 + i][c0] = make_float4(S[i][0], S[i][1], S[i][2], S[i][3]);
        __syncthreads();

#pragma unroll
        for (int k = 0; k < 64; k++) {
            float4 vv = *(const float4*)&Vs[k][c0];
            float va[4] = {vv.x, vv.y, vv.z, vv.w};
            float p0 = KPs[r0 + 0][k], p1 = KPs[r0 + 1][k];
            float p2 = KPs[r0 + 2][k], p3 = KPs[r0 + 3][k];
#pragma unroll
            for (int j = 0; j < 4; j++) {
                O[0][j] = fmaf(p0, va[j], O[0][j]);
                O[1][j] = fmaf(p1, va[j], O[1][j]);
                O[2][j] = fmaf(p2, va[j], O[2][j]);
                O[3][j] = fmaf(p3, va[j], O[3][j]);
            }
        }
        __syncthreads();
    }

    const int b = bh >> 4, h = bh & 15;
#pragma unroll
    for (int i = 0; i < 4; i++) {
        float inv = 1.f / l[i];
        int q = qt * 64 + r0 + i;
        float4 o = make_float4(O[i][0] * inv, O[i][1] * inv,
                               O[i][2] * inv, O[i][3] * inv);
        *(float4*)(ctx + ((size_t)(b * SEQ + q)) * DM + h * HD + c0) = o;
    }
}

// ---------------------------------------------------------------------------
// Launch
// ---------------------------------------------------------------------------
extern "C" void kernel_launch(void* const* d_in, const int* in_sizes, int n_in,
                              void* d_out, int out_size)
{
    const float* x  = (const float*)d_in[0];
    const float* wq = (const float*)d_in[1];
    const float* bq = (const float*)d_in[2];
    const float* wk = (const float*)d_in[3];
    const float* bk = (const float*)d_in[4];
    const float* wv = (const float*)d_in[5];
    const float* bv = (const float*)d_in[6];
    const float* wo = (const float*)d_in[7];
    const float* bo = (const float*)d_in[8];
    float* out = (float*)d_out;

    float *q, *k, *v, *ctx;
    cudaGetSymbolAddress((void**)&q,   g_q);
    cudaGetSymbolAddress((void**)&k,   g_k);
    cudaGetSymbolAddress((void**)&v,   g_v);
    cudaGetSymbolAddress((void**)&ctx, g_ctx);

    dim3 gg(DM / 128, MROWS / 128);   // (8, 64)
    const float qscale = 0.125f;      // 1/sqrt(64)

    gemm_tf32<<<gg, 256>>>(x, wq, bq, q, 1, qscale);
    gemm_tf32<<<gg, 256>>>(x, wk, bk, k, 1, 1.0f);
    gemm_tf32<<<gg, 256>>>(x, wv, bv, v, 1, 1.0f);

    flash_attn<<<dim3(SEQ / 64, BATCH * NH), 256>>>(q, k, v, ctx);

    gemm_tf32<<<gg, 256>>>(ctx, wo, bo, out, 0, 1.0f);
}

// round 6
// speedup vs baseline: 2.7633x; 1.7367x over previous
#include <cuda_runtime.h>
#include <math.h>

#define BATCH 4
#define SEQ   2048
#define DM    1024
#define NH    16
#define HD    64
#define MROWS (BATCH * SEQ)   // 8192

__device__ float g_q[BATCH * NH * SEQ * HD];
__device__ float g_k[BATCH * NH * SEQ * HD];
__device__ float g_v[BATCH * NH * SEQ * HD];
__device__ float g_ctx[MROWS * DM];

// ---------------------------------------------------------------------------
// tf32 helpers
// ---------------------------------------------------------------------------
__device__ __forceinline__ unsigned f2tf32(float f) {
    unsigned u;
    asm("cvt.rna.tf32.f32 %0, %1;" : "=r"(u) : "f"(f));
    return u;
}

__device__ __forceinline__ void mma_tf32(float* d, const unsigned* a,
                                         unsigned b0, unsigned b1) {
    asm volatile(
        "mma.sync.aligned.m16n8k8.row.col.f32.tf32.tf32.f32 "
        "{%0,%1,%2,%3}, {%4,%5,%6,%7}, {%8,%9}, {%0,%1,%2,%3};\n"
        : "+f"(d[0]), "+f"(d[1]), "+f"(d[2]), "+f"(d[3])
        : "r"(a[0]), "r"(a[1]), "r"(a[2]), "r"(a[3]), "r"(b0), "r"(b1));
}

// ---------------------------------------------------------------------------
// tf32 tensor-core GEMM (unchanged from R2)
// ---------------------------------------------------------------------------
__global__ __launch_bounds__(256) void gemm_tf32(
    const float* __restrict__ A, const float* __restrict__ B,
    const float* __restrict__ bias, float* __restrict__ C,
    int qkv, float scale)
{
    __shared__ unsigned As[128][36];
    __shared__ unsigned Bs[32][132];

    const int tid   = threadIdx.x;
    const int lane  = tid & 31;
    const int warp  = tid >> 5;
    const int warpM = warp & 3;
    const int warpN = warp >> 2;
    const int g     = lane >> 2;
    const int t     = lane & 3;
    const int rowBase = blockIdx.y * 128;
    const int colBase = blockIdx.x * 128;

    float d[2][8][4];
#pragma unroll
    for (int mt = 0; mt < 2; mt++)
#pragma unroll
        for (int nt = 0; nt < 8; nt++)
#pragma unroll
            for (int j = 0; j < 4; j++) d[mt][nt][j] = 0.f;

    for (int k0 = 0; k0 < DM; k0 += 32) {
#pragma unroll
        for (int it = 0; it < 4; it++) {
            int linear = tid + it * 256;
            int r  = linear >> 3;
            int c4 = (linear & 7) * 4;
            float4 v = *(const float4*)(A + (size_t)(rowBase + r) * DM + k0 + c4);
            uint4 u = make_uint4(f2tf32(v.x), f2tf32(v.y), f2tf32(v.z), f2tf32(v.w));
            *(uint4*)&As[r][c4] = u;
        }
#pragma unroll
        for (int it = 0; it < 4; it++) {
            int linear = tid + it * 256;
            int r  = linear >> 5;
            int c4 = (linear & 31) * 4;
            float4 v = *(const float4*)(B + (size_t)(k0 + r) * DM + colBase + c4);
            uint4 u = make_uint4(f2tf32(v.x), f2tf32(v.y), f2tf32(v.z), f2tf32(v.w));
            *(uint4*)&Bs[r][c4] = u;
        }
        __syncthreads();

#pragma unroll
        for (int kk = 0; kk < 32; kk += 8) {
            unsigned a[2][4];
#pragma unroll
            for (int mt = 0; mt < 2; mt++) {
                int rb = warpM * 32 + mt * 16;
                a[mt][0] = As[rb + g    ][kk + t];
                a[mt][1] = As[rb + g + 8][kk + t];
                a[mt][2] = As[rb + g    ][kk + t + 4];
                a[mt][3] = As[rb + g + 8][kk + t + 4];
            }
#pragma unroll
            for (int nt = 0; nt < 8; nt++) {
                int cb = warpN * 64 + nt * 8;
                unsigned b0 = Bs[kk + t    ][cb + g];
                unsigned b1 = Bs[kk + t + 4][cb + g];
                mma_tf32(d[0][nt], a[0], b0, b1);
                mma_tf32(d[1][nt], a[1], b0, b1);
            }
        }
        __syncthreads();
    }

#pragma unroll
    for (int mt = 0; mt < 2; mt++) {
        int row0 = rowBase + warpM * 32 + mt * 16 + g;
#pragma unroll
        for (int nt = 0; nt < 8; nt++) {
            int col = colBase + warpN * 64 + nt * 8 + 2 * t;
            float bb0 = bias[col], bb1 = bias[col + 1];
            float v00 = (d[mt][nt][0] + bb0) * scale;
            float v01 = (d[mt][nt][1] + bb1) * scale;
            float v10 = (d[mt][nt][2] + bb0) * scale;
            float v11 = (d[mt][nt][3] + bb1) * scale;
            if (!qkv) {
                *(float2*)(C + (size_t)row0 * DM + col)       = make_float2(v00, v01);
                *(float2*)(C + (size_t)(row0 + 8) * DM + col) = make_float2(v10, v11);
            } else {
                int h = col >> 6, hd = col & 63;
                int b0i = row0 >> 11, s0 = row0 & 2047;
                int r1 = row0 + 8;
                int b1i = r1 >> 11, s1 = r1 & 2047;
                size_t base0 = (((size_t)(b0i * NH + h) * SEQ) + s0) * HD + hd;
                size_t base1 = (((size_t)(b1i * NH + h) * SEQ) + s1) * HD + hd;
                C[base0]     = v00;
                C[base0 + 1] = v01;
                C[base1]     = v10;
                C[base1 + 1] = v11;
            }
        }
    }
}

// ---------------------------------------------------------------------------
// Tensor-core flash attention (tf32), causal. Q pre-scaled by 1/sqrt(HD).
// Tile: 128 queries x 64 keys. 256 threads, 8 warps; warp = 16 q-rows x 64 k.
// Dynamic smem: Qs[128][68] | Ks[64][68] | Vs[64][72] | Ps[128][68] (tf32).
// ---------------------------------------------------------------------------
#define FA_SMEM ((128*68 + 64*68 + 64*72 + 128*68) * 4)

__global__ __launch_bounds__(256, 2) void flash_attn_tc(
    const float* __restrict__ Q, const float* __restrict__ K,
    const float* __restrict__ V, float* __restrict__ ctx)
{
    extern __shared__ unsigned sm_[];
    unsigned (*Qs)[68] = (unsigned(*)[68])sm_;
    unsigned (*Ks)[68] = (unsigned(*)[68])(sm_ + 128 * 68);
    unsigned (*Vs)[72] = (unsigned(*)[72])(sm_ + 128 * 68 + 64 * 68);
    unsigned (*Ps)[68] = (unsigned(*)[68])(sm_ + 128 * 68 + 64 * 68 + 64 * 72);

    const int tid  = threadIdx.x;
    const int lane = tid & 31;
    const int warp = tid >> 5;
    const int g    = lane >> 2;   // 0..7
    const int t    = lane & 3;    // 0..3
    const int qt   = blockIdx.x;
    const int bh   = blockIdx.y;
    const int Q0   = qt * 128;
    const int rb   = warp * 16;

    const size_t base = (size_t)bh * SEQ * HD;

    // stage Q tile (tf32) into Qs
    {
        const float* Qb = Q + base + (size_t)Q0 * HD;
#pragma unroll
        for (int it = 0; it < 8; it++) {
            int idx = tid + it * 256;        // 0..2047 float4s
            int r   = idx >> 4;              // 0..127
            int c4  = (idx & 15) * 4;        // 0..60
            float4 v = *(const float4*)(Qb + r * HD + c4);
            Qs[r][c4 + 0] = f2tf32(v.x); Qs[r][c4 + 1] = f2tf32(v.y);
            Qs[r][c4 + 2] = f2tf32(v.z); Qs[r][c4 + 3] = f2tf32(v.w);
        }
    }

    float m[2] = {-INFINITY, -INFINITY};
    float l[2] = {0.f, 0.f};
    float O[8][4];
#pragma unroll
    for (int nf = 0; nf < 8; nf++)
#pragma unroll
        for (int j = 0; j < 4; j++) O[nf][j] = 0.f;

    const int ktmax = 2 * qt + 1;
    for (int kt = 0; kt <= ktmax; kt++) {
        __syncthreads();   // prior readers of Ks/Vs (and Qs staging) done
        {
            const float* Kb = K + base + (size_t)kt * 64 * HD;
            const float* Vb = V + base + (size_t)kt * 64 * HD;
#pragma unroll
            for (int it = 0; it < 4; it++) {
                int idx = tid + it * 256;    // 0..1023 float4s
                int r   = idx >> 4;          // 0..63
                int c4  = (idx & 15) * 4;
                float4 kv = *(const float4*)(Kb + r * HD + c4);
                Ks[r][c4 + 0] = f2tf32(kv.x); Ks[r][c4 + 1] = f2tf32(kv.y);
                Ks[r][c4 + 2] = f2tf32(kv.z); Ks[r][c4 + 3] = f2tf32(kv.w);
                float4 vv = *(const float4*)(Vb + r * HD + c4);
                Vs[r][c4 + 0] = f2tf32(vv.x); Vs[r][c4 + 1] = f2tf32(vv.y);
                Vs[r][c4 + 2] = f2tf32(vv.z); Vs[r][c4 + 3] = f2tf32(vv.w);
            }
        }
        __syncthreads();

        // S = Q K^T
        float S[8][4];
#pragma unroll
        for (int nf = 0; nf < 8; nf++)
#pragma unroll
            for (int j = 0; j < 4; j++) S[nf][j] = 0.f;

#pragma unroll
        for (int kk = 0; kk < 8; kk++) {
            unsigned a[4];
            a[0] = Qs[rb + g    ][kk * 8 + t];
            a[1] = Qs[rb + g + 8][kk * 8 + t];
            a[2] = Qs[rb + g    ][kk * 8 + t + 4];
            a[3] = Qs[rb + g + 8][kk * 8 + t + 4];
#pragma unroll
            for (int nf = 0; nf < 8; nf++) {
                unsigned b0 = Ks[nf * 8 + g][kk * 8 + t];
                unsigned b1 = Ks[nf * 8 + g][kk * 8 + t + 4];
                mma_tf32(S[nf], a, b0, b1);
            }
        }

        // causal mask on the two diagonal-adjacent tiles
        if (kt >= 2 * qt) {
            int kb = kt * 64;
            int rlo = Q0 + rb + g, rhi = rlo + 8;
#pragma unroll
            for (int nf = 0; nf < 8; nf++) {
                int k0 = kb + nf * 8 + 2 * t;
                if (k0     > rlo) S[nf][0] = -INFINITY;
                if (k0 + 1 > rlo) S[nf][1] = -INFINITY;
                if (k0     > rhi) S[nf][2] = -INFINITY;
                if (k0 + 1 > rhi) S[nf][3] = -INFINITY;
            }
        }

        // online softmax (rows rb+g and rb+g+8; quad = 4 lanes sharing row)
#pragma unroll
        for (int h2 = 0; h2 < 2; h2++) {
            float mx = -INFINITY;
#pragma unroll
            for (int nf = 0; nf < 8; nf++)
                mx = fmaxf(mx, fmaxf(S[nf][2 * h2], S[nf][2 * h2 + 1]));
            mx = fmaxf(mx, __shfl_xor_sync(0xffffffffu, mx, 1));
            mx = fmaxf(mx, __shfl_xor_sync(0xffffffffu, mx, 2));
            float mn = fmaxf(m[h2], mx);
            float sc = __expf(m[h2] - mn);
            m[h2] = mn;
            float rs = 0.f;
#pragma unroll
            for (int nf = 0; nf < 8; nf++) {
                float e0 = __expf(S[nf][2 * h2]     - mn);
                float e1 = __expf(S[nf][2 * h2 + 1] - mn);
                S[nf][2 * h2] = e0; S[nf][2 * h2 + 1] = e1;
                rs += e0 + e1;
            }
            rs += __shfl_xor_sync(0xffffffffu, rs, 1);
            rs += __shfl_xor_sync(0xffffffffu, rs, 2);
            l[h2] = l[h2] * sc + rs;
#pragma unroll
            for (int nf = 0; nf < 8; nf++) {
                O[nf][2 * h2]     *= sc;
                O[nf][2 * h2 + 1] *= sc;
            }
        }

        // P -> smem (tf32); prior readers fenced by the two syncs above
#pragma unroll
        for (int nf = 0; nf < 8; nf++) {
            int c = nf * 8 + 2 * t;
            *(uint2*)&Ps[rb + g    ][c] = make_uint2(f2tf32(S[nf][0]), f2tf32(S[nf][1]));
            *(uint2*)&Ps[rb + g + 8][c] = make_uint2(f2tf32(S[nf][2]), f2tf32(S[nf][3]));
        }
        __syncthreads();

        // O += P V
#pragma unroll
        for (int kk = 0; kk < 8; kk++) {
            unsigned a[4];
            a[0] = Ps[rb + g    ][kk * 8 + t];
            a[1] = Ps[rb + g + 8][kk * 8 + t];
            a[2] = Ps[rb + g    ][kk * 8 + t + 4];
            a[3] = Ps[rb + g + 8][kk * 8 + t + 4];
#pragma unroll
            for (int nf = 0; nf < 8; nf++) {
                unsigned b0 = Vs[kk * 8 + t    ][nf * 8 + g];
                unsigned b1 = Vs[kk * 8 + t + 4][nf * 8 + g];
                mma_tf32(O[nf], a, b0, b1);
            }
        }
    }

    // epilogue: normalize, write ctx [b*SEQ + q][h*64 + d]
    const int b = bh >> 4, hh = bh & 15;
#pragma unroll
    for (int h2 = 0; h2 < 2; h2++) {
        float inv = 1.f / l[h2];
        int row = Q0 + rb + g + 8 * h2;
        float* dst = ctx + ((size_t)(b * SEQ + row)) * DM + hh * HD;
#pragma unroll
        for (int nf = 0; nf < 8; nf++) {
            int c = nf * 8 + 2 * t;
            *(float2*)(dst + c) =
                make_float2(O[nf][2 * h2] * inv, O[nf][2 * h2 + 1] * inv);
        }
    }
}

// ---------------------------------------------------------------------------
// Launch
// ---------------------------------------------------------------------------
extern "C" void kernel_launch(void* const* d_in, const int* in_sizes, int n_in,
                              void* d_out, int out_size)
{
    const float* x  = (const float*)d_in[0];
    const float* wq = (const float*)d_in[1];
    const float* bq = (const float*)d_in[2];
    const float* wk = (const float*)d_in[3];
    const float* bk = (const float*)d_in[4];
    const float* wv = (const float*)d_in[5];
    const float* bv = (const float*)d_in[6];
    const float* wo = (const float*)d_in[7];
    const float* bo = (const float*)d_in[8];
    float* out = (float*)d_out;

    float *q, *k, *v, *ctx;
    cudaGetSymbolAddress((void**)&q,   g_q);
    cudaGetSymbolAddress((void**)&k,   g_k);
    cudaGetSymbolAddress((void**)&v,   g_v);
    cudaGetSymbolAddress((void**)&ctx, g_ctx);

    cudaFuncSetAttribute(flash_attn_tc,
                         cudaFuncAttributeMaxDynamicSharedMemorySize, FA_SMEM);

    dim3 gg(DM / 128, MROWS / 128);   // (8, 64)
    const float qscale = 0.125f;      // 1/sqrt(64)

    gemm_tf32<<<gg, 256>>>(x, wq, bq, q, 1, qscale);
    gemm_tf32<<<gg, 256>>>(x, wk, bk, k, 1, 1.0f);
    gemm_tf32<<<gg, 256>>>(x, wv, bv, v, 1, 1.0f);

    flash_attn_tc<<<dim3(SEQ / 128, BATCH * NH), 256, FA_SMEM>>>(q, k, v, ctx);

    gemm_tf32<<<gg, 256>>>(ctx, wo, bo, out, 0, 1.0f);
}

// round 7
// speedup vs baseline: 3.1173x; 1.1281x over previous
#include <cuda_runtime.h>
#include <math.h>

#define BATCH 4
#define SEQ   2048
#define DM    1024
#define NH    16
#define HD    64
#define MROWS (BATCH * SEQ)   // 8192

__device__ float g_q[BATCH * NH * SEQ * HD];
__device__ float g_k[BATCH * NH * SEQ * HD];
__device__ float g_v[BATCH * NH * SEQ * HD];
__device__ float g_ctx[MROWS * DM];
__device__ float g_xr[MROWS * DM];      // tf32-rounded x
__device__ float g_wr[4][DM * DM];      // tf32-rounded wq,wk,wv,wo

// ---------------------------------------------------------------------------
// helpers
// ---------------------------------------------------------------------------
__device__ __forceinline__ unsigned f2tf32(float f) {
    unsigned u;
    asm("cvt.rna.tf32.f32 %0, %1;" : "=r"(u) : "f"(f));
    return u;
}

__device__ __forceinline__ void mma_tf32(float* d, const unsigned* a,
                                         unsigned b0, unsigned b1) {
    asm volatile(
        "mma.sync.aligned.m16n8k8.row.col.f32.tf32.tf32.f32 "
        "{%0,%1,%2,%3}, {%4,%5,%6,%7}, {%8,%9}, {%0,%1,%2,%3};\n"
        : "+f"(d[0]), "+f"(d[1]), "+f"(d[2]), "+f"(d[3])
        : "r"(a[0]), "r"(a[1]), "r"(a[2]), "r"(a[3]), "r"(b0), "r"(b1));
}

__device__ __forceinline__ unsigned saddr(const void* p) {
    return (unsigned)__cvta_generic_to_shared(p);
}
__device__ __forceinline__ void cp16(unsigned d, const void* s) {
    asm volatile("cp.async.cg.shared.global [%0], [%1], 16;" :: "r"(d), "l"(s));
}
#define CP_COMMIT asm volatile("cp.async.commit_group;")
#define CP_WAIT0  asm volatile("cp.async.wait_group 0;")

// ---------------------------------------------------------------------------
// elementwise tf32 pre-round (float4)
// ---------------------------------------------------------------------------
__global__ void round_tf32_k(const float* __restrict__ in,
                             float* __restrict__ out, int n4)
{
    int i = blockIdx.x * blockDim.x + threadIdx.x;
    if (i < n4) {
        float4 v = ((const float4*)in)[i];
        float4 o;
        o.x = __uint_as_float(f2tf32(v.x));
        o.y = __uint_as_float(f2tf32(v.y));
        o.z = __uint_as_float(f2tf32(v.z));
        o.w = __uint_as_float(f2tf32(v.w));
        ((float4*)out)[i] = o;
    }
}

// ---------------------------------------------------------------------------
// tf32 GEMM, cp.async double-buffered. Inputs pre-rounded to tf32.
// C = (A @ B + bias) * scale; qkv!=0 -> scatter to [b,h,s,hd] + tf32-round.
// BM=BN=128, BK=32, 256 threads, warp tile 32x64.
// ---------------------------------------------------------------------------
#define GA_STR 36
#define GB_STR 132
#define G_SMEM ((2 * 128 * GA_STR + 2 * 32 * GB_STR) * 4)   // 70656 B

__device__ __forceinline__ void gemm_stage(
    const float* __restrict__ A, const float* __restrict__ B,
    float* Ab, float* Bb, int rowBase, int colBase, int k0, int tid)
{
#pragma unroll
    for (int it = 0; it < 4; it++) {
        int idx = tid + it * 256;
        int r  = idx >> 3;              // 0..127
        int c4 = (idx & 7) * 4;         // 0..28
        cp16(saddr(Ab + r * GA_STR + c4),
             A + (size_t)(rowBase + r) * DM + k0 + c4);
        int rb = idx >> 5;              // 0..31
        int cb = (idx & 31) * 4;        // 0..124
        cp16(saddr(Bb + rb * GB_STR + cb),
             B + (size_t)(k0 + rb) * DM + colBase + cb);
    }
}

__global__ __launch_bounds__(256, 2) void gemm_tf32_db(
    const float* __restrict__ A, const float* __restrict__ B,
    const float* __restrict__ bias, float* __restrict__ C,
    int qkv, float scale)
{
    extern __shared__ float gsm[];
    float* As = gsm;                       // [2][128][36]
    float* Bs = gsm + 2 * 128 * GA_STR;    // [2][32][132]

    const int tid   = threadIdx.x;
    const int lane  = tid & 31;
    const int warp  = tid >> 5;
    const int warpM = warp & 3;
    const int warpN = warp >> 2;
    const int g     = lane >> 2;
    const int t     = lane & 3;
    const int rowBase = blockIdx.y * 128;
    const int colBase = blockIdx.x * 128;

    float d[2][8][4];
#pragma unroll
    for (int mt = 0; mt < 2; mt++)
#pragma unroll
        for (int nt = 0; nt < 8; nt++)
#pragma unroll
            for (int j = 0; j < 4; j++) d[mt][nt][j] = 0.f;

    gemm_stage(A, B, As, Bs, rowBase, colBase, 0, tid);
    CP_COMMIT;

    int buf = 0;
    for (int itn = 0; itn < 32; itn++) {
        CP_WAIT0;
        __syncthreads();   // stage ready AND all readers of other buffer done
        if (itn < 31) {
            gemm_stage(A, B, As + (buf ^ 1) * 128 * GA_STR,
                       Bs + (buf ^ 1) * 32 * GB_STR,
                       rowBase, colBase, (itn + 1) * 32, tid);
            CP_COMMIT;
        }
        const float* Ab = As + buf * 128 * GA_STR;
        const float* Bb = Bs + buf * 32 * GB_STR;
#pragma unroll
        for (int kk = 0; kk < 32; kk += 8) {
            unsigned a[2][4];
#pragma unroll
            for (int mt = 0; mt < 2; mt++) {
                int rb = warpM * 32 + mt * 16;
                a[mt][0] = __float_as_uint(Ab[(rb + g    ) * GA_STR + kk + t]);
                a[mt][1] = __float_as_uint(Ab[(rb + g + 8) * GA_STR + kk + t]);
                a[mt][2] = __float_as_uint(Ab[(rb + g    ) * GA_STR + kk + t + 4]);
                a[mt][3] = __float_as_uint(Ab[(rb + g + 8) * GA_STR + kk + t + 4]);
            }
#pragma unroll
            for (int nt = 0; nt < 8; nt++) {
                int cb = warpN * 64 + nt * 8;
                unsigned b0 = __float_as_uint(Bb[(kk + t    ) * GB_STR + cb + g]);
                unsigned b1 = __float_as_uint(Bb[(kk + t + 4) * GB_STR + cb + g]);
                mma_tf32(d[0][nt], a[0], b0, b1);
                mma_tf32(d[1][nt], a[1], b0, b1);
            }
        }
        buf ^= 1;
    }

#pragma unroll
    for (int mt = 0; mt < 2; mt++) {
        int row0 = rowBase + warpM * 32 + mt * 16 + g;
#pragma unroll
        for (int nt = 0; nt < 8; nt++) {
            int col = colBase + warpN * 64 + nt * 8 + 2 * t;
            float bb0 = bias[col], bb1 = bias[col + 1];
            float v00 = (d[mt][nt][0] + bb0) * scale;
            float v01 = (d[mt][nt][1] + bb1) * scale;
            float v10 = (d[mt][nt][2] + bb0) * scale;
            float v11 = (d[mt][nt][3] + bb1) * scale;
            if (!qkv) {
                *(float2*)(C + (size_t)row0 * DM + col)       = make_float2(v00, v01);
                *(float2*)(C + (size_t)(row0 + 8) * DM + col) = make_float2(v10, v11);
            } else {
                // tf32-round QKV so flash can consume raw bits
                v00 = __uint_as_float(f2tf32(v00));
                v01 = __uint_as_float(f2tf32(v01));
                v10 = __uint_as_float(f2tf32(v10));
                v11 = __uint_as_float(f2tf32(v11));
                int h = col >> 6, hd = col & 63;
                int b0i = row0 >> 11, s0 = row0 & 2047;
                int r1 = row0 + 8;
                int b1i = r1 >> 11, s1 = r1 & 2047;
                size_t base0 = (((size_t)(b0i * NH + h) * SEQ) + s0) * HD + hd;
                size_t base1 = (((size_t)(b1i * NH + h) * SEQ) + s1) * HD + hd;
                C[base0]     = v00;
                C[base0 + 1] = v01;
                C[base1]     = v10;
                C[base1 + 1] = v11;
            }
        }
    }
}

// ---------------------------------------------------------------------------
// Flash attention v2: tf32 mma, cp.async double-buffered K/V, register-only P
// (accumulator->A-fragment quad shuffles). 1 barrier per k-tile.
// Tile: 128 q x 64 k, 256 threads, warp = 16 q-rows x 64 keys.
// smem: Qs[128][68] | Ks[2][64][68] | Vs[2][64][72]
// ---------------------------------------------------------------------------
#define QS_STR 68
#define KS_STR 68
#define VS_STR 72
#define FA_SMEM ((128 * QS_STR + 2 * 64 * KS_STR + 2 * 64 * VS_STR) * 4)  // 106496

__device__ __forceinline__ void fa_stage(
    const float* __restrict__ Kb, const float* __restrict__ Vb,
    float* Kd, float* Vd, int tid)
{
#pragma unroll
    for (int it = 0; it < 4; it++) {
        int idx = tid + it * 256;       // 0..1023
        int r   = idx >> 4;             // 0..63
        int c4  = (idx & 15) * 4;       // 0..60
        cp16(saddr(Kd + r * KS_STR + c4), Kb + r * HD + c4);
        cp16(saddr(Vd + r * VS_STR + c4), Vb + r * HD + c4);
    }
}

__global__ __launch_bounds__(256, 2) void flash_attn_tc2(
    const float* __restrict__ Q, const float* __restrict__ K,
    const float* __restrict__ V, float* __restrict__ ctx)
{
    extern __shared__ float fsm[];
    float* Qs = fsm;                                   // [128][68]
    float* Ks = fsm + 128 * QS_STR;                    // [2][64][68]
    float* Vs = fsm + 128 * QS_STR + 2 * 64 * KS_STR;  // [2][64][72]

    const int tid  = threadIdx.x;
    const int lane = tid & 31;
    const int warp = tid >> 5;
    const int g    = lane >> 2;
    const int t    = lane & 3;
    const int qt   = blockIdx.x;
    const int bh   = blockIdx.y;
    const int Q0   = qt * 128;
    const int rb   = warp * 16;

    const size_t base = (size_t)bh * SEQ * HD;

    // prologue: stage Q and K/V tile 0 (one cp.async group)
    {
        const float* Qb = Q + base + (size_t)Q0 * HD;
#pragma unroll
        for (int it = 0; it < 8; it++) {
            int idx = tid + it * 256;   // 0..2047
            int r   = idx >> 4;         // 0..127
            int c4  = (idx & 15) * 4;
            cp16(saddr(Qs + r * QS_STR + c4), Qb + r * HD + c4);
        }
        fa_stage(K + base, V + base, Ks, Vs, tid);
        CP_COMMIT;
    }

    float m[2] = {-INFINITY, -INFINITY};
    float l[2] = {0.f, 0.f};
    float O[8][4];
#pragma unroll
    for (int nf = 0; nf < 8; nf++)
#pragma unroll
        for (int j = 0; j < 4; j++) O[nf][j] = 0.f;

    int buf = 0;
    const int ktmax = 2 * qt + 1;
    for (int kt = 0; kt <= ktmax; kt++) {
        CP_WAIT0;
        __syncthreads();   // stage kt ready; prior readers of other buf done
        if (kt < ktmax) {
            fa_stage(K + base + (size_t)(kt + 1) * 64 * HD,
                     V + base + (size_t)(kt + 1) * 64 * HD,
                     Ks + (buf ^ 1) * 64 * KS_STR,
                     Vs + (buf ^ 1) * 64 * VS_STR, tid);
            CP_COMMIT;
        }
        const float* Kc = Ks + buf * 64 * KS_STR;
        const float* Vc = Vs + buf * 64 * VS_STR;

        // S = Q K^T
        float S[8][4];
#pragma unroll
        for (int nf = 0; nf < 8; nf++)
#pragma unroll
            for (int j = 0; j < 4; j++) S[nf][j] = 0.f;

#pragma unroll
        for (int kk = 0; kk < 8; kk++) {
            unsigned a[4];
            a[0] = __float_as_uint(Qs[(rb + g    ) * QS_STR + kk * 8 + t]);
            a[1] = __float_as_uint(Qs[(rb + g + 8) * QS_STR + kk * 8 + t]);
            a[2] = __float_as_uint(Qs[(rb + g    ) * QS_STR + kk * 8 + t + 4]);
            a[3] = __float_as_uint(Qs[(rb + g + 8) * QS_STR + kk * 8 + t + 4]);
#pragma unroll
            for (int nf = 0; nf < 8; nf++) {
                unsigned b0 = __float_as_uint(Kc[(nf * 8 + g) * KS_STR + kk * 8 + t]);
                unsigned b1 = __float_as_uint(Kc[(nf * 8 + g) * KS_STR + kk * 8 + t + 4]);
                mma_tf32(S[nf], a, b0, b1);
            }
        }

        if (kt >= 2 * qt) {   // causal mask (diagonal-adjacent tiles)
            int kb = kt * 64;
            int rlo = Q0 + rb + g, rhi = rlo + 8;
#pragma unroll
            for (int nf = 0; nf < 8; nf++) {
                int k0 = kb + nf * 8 + 2 * t;
                if (k0     > rlo) S[nf][0] = -INFINITY;
                if (k0 + 1 > rlo) S[nf][1] = -INFINITY;
                if (k0     > rhi) S[nf][2] = -INFINITY;
                if (k0 + 1 > rhi) S[nf][3] = -INFINITY;
            }
        }

        // online softmax
#pragma unroll
        for (int h2 = 0; h2 < 2; h2++) {
            float mx = -INFINITY;
#pragma unroll
            for (int nf = 0; nf < 8; nf++)
                mx = fmaxf(mx, fmaxf(S[nf][2 * h2], S[nf][2 * h2 + 1]));
            mx = fmaxf(mx, __shfl_xor_sync(0xffffffffu, mx, 1));
            mx = fmaxf(mx, __shfl_xor_sync(0xffffffffu, mx, 2));
            float mn = fmaxf(m[h2], mx);
            float sc = __expf(m[h2] - mn);
            m[h2] = mn;
            float rs = 0.f;
#pragma unroll
            for (int nf = 0; nf < 8; nf++) {
                float e0 = __expf(S[nf][2 * h2]     - mn);
                float e1 = __expf(S[nf][2 * h2 + 1] - mn);
                S[nf][2 * h2] = e0; S[nf][2 * h2 + 1] = e1;
                rs += e0 + e1;
            }
            rs += __shfl_xor_sync(0xffffffffu, rs, 1);
            rs += __shfl_xor_sync(0xffffffffu, rs, 2);
            l[h2] = l[h2] * sc + rs;
#pragma unroll
            for (int nf = 0; nf < 8; nf++) {
                O[nf][2 * h2]     *= sc;
                O[nf][2 * h2 + 1] *= sc;
            }
        }

        // O += P V  — P converted C-frag -> A-frag via quad shuffles
        {
            const int srcA = (lane & 28) | (t >> 1);
            const int srcB = srcA + 2;
            const bool odd = (t & 1);
#pragma unroll
            for (int kk = 0; kk < 8; kk++) {
                float s0A = __shfl_sync(0xffffffffu, S[kk][0], srcA);
                float s1A = __shfl_sync(0xffffffffu, S[kk][1], srcA);
                float s2A = __shfl_sync(0xffffffffu, S[kk][2], srcA);
                float s3A = __shfl_sync(0xffffffffu, S[kk][3], srcA);
                float s0B = __shfl_sync(0xffffffffu, S[kk][0], srcB);
                float s1B = __shfl_sync(0xffffffffu, S[kk][1], srcB);
                float s2B = __shfl_sync(0xffffffffu, S[kk][2], srcB);
                float s3B = __shfl_sync(0xffffffffu, S[kk][3], srcB);
                unsigned a[4];
                a[0] = f2tf32(odd ? s1A : s0A);
                a[1] = f2tf32(odd ? s3A : s2A);
                a[2] = f2tf32(odd ? s1B : s0B);
                a[3] = f2tf32(odd ? s3B : s2B);
#pragma unroll
                for (int nf = 0; nf < 8; nf++) {
                    unsigned b0 = __float_as_uint(Vc[(kk * 8 + t    ) * VS_STR + nf * 8 + g]);
                    unsigned b1 = __float_as_uint(Vc[(kk * 8 + t + 4) * VS_STR + nf * 8 + g]);
                    mma_tf32(O[nf], a, b0, b1);
                }
            }
        }
        buf ^= 1;
        // no end barrier: next iteration's top barrier orders buffer reuse
    }

    // epilogue: normalize, tf32-round, write ctx [b*SEQ + q][h*64 + d]
    const int b = bh >> 4, hh = bh & 15;
#pragma unroll
    for (int h2 = 0; h2 < 2; h2++) {
        float inv = 1.f / l[h2];
        int row = Q0 + rb + g + 8 * h2;
        float* dst = ctx + ((size_t)(b * SEQ + row)) * DM + hh * HD;
#pragma unroll
        for (int nf = 0; nf < 8; nf++) {
            int c = nf * 8 + 2 * t;
            float o0 = __uint_as_float(f2tf32(O[nf][2 * h2]     * inv));
            float o1 = __uint_as_float(f2tf32(O[nf][2 * h2 + 1] * inv));
            *(float2*)(dst + c) = make_float2(o0, o1);
        }
    }
}

// ---------------------------------------------------------------------------
// Launch
// ---------------------------------------------------------------------------
extern "C" void kernel_launch(void* const* d_in, const int* in_sizes, int n_in,
                              void* d_out, int out_size)
{
    const float* x  = (const float*)d_in[0];
    const float* wq = (const float*)d_in[1];
    const float* bq = (const float*)d_in[2];
    const float* wk = (const float*)d_in[3];
    const float* bk = (const float*)d_in[4];
    const float* wv = (const float*)d_in[5];
    const float* bv = (const float*)d_in[6];
    const float* wo = (const float*)d_in[7];
    const float* bo = (const float*)d_in[8];
    float* out = (float*)d_out;

    float *q, *k, *v, *ctx, *xr, *wr;
    cudaGetSymbolAddress((void**)&q,   g_q);
    cudaGetSymbolAddress((void**)&k,   g_k);
    cudaGetSymbolAddress((void**)&v,   g_v);
    cudaGetSymbolAddress((void**)&ctx, g_ctx);
    cudaGetSymbolAddress((void**)&xr,  g_xr);
    cudaGetSymbolAddress((void**)&wr,  g_wr);
    float* wqr = wr;
    float* wkr = wr + DM * DM;
    float* wvr = wr + 2 * DM * DM;
    float* wor = wr + 3 * DM * DM;

    cudaFuncSetAttribute(gemm_tf32_db,
                         cudaFuncAttributeMaxDynamicSharedMemorySize, G_SMEM);
    cudaFuncSetAttribute(flash_attn_tc2,
                         cudaFuncAttributeMaxDynamicSharedMemorySize, FA_SMEM);

    // pre-round inputs to tf32
    {
        int n4x = MROWS * DM / 4;          // 2097152
        int n4w = DM * DM / 4;             // 262144
        round_tf32_k<<<(n4x + 255) / 256, 256>>>(x,  xr,  n4x);
        round_tf32_k<<<(n4w + 255) / 256, 256>>>(wq, wqr, n4w);
        round_tf32_k<<<(n4w + 255) / 256, 256>>>(wk, wkr, n4w);
        round_tf32_k<<<(n4w + 255) / 256, 256>>>(wv, wvr, n4w);
        round_tf32_k<<<(n4w + 255) / 256, 256>>>(wo, wor, n4w);
    }

    dim3 gg(DM / 128, MROWS / 128);   // (8, 64)
    const float qscale = 0.125f;      // 1/sqrt(64)

    gemm_tf32_db<<<gg, 256, G_SMEM>>>(xr, wqr, bq, q, 1, qscale);
    gemm_tf32_db<<<gg, 256, G_SMEM>>>(xr, wkr, bk, k, 1, 1.0f);
    gemm_tf32_db<<<gg, 256, G_SMEM>>>(xr, wvr, bv, v, 1, 1.0f);

    flash_attn_tc2<<<dim3(SEQ / 128, BATCH * NH), 256, FA_SMEM>>>(q, k, v, ctx);

    gemm_tf32_db<<<gg, 256, G_SMEM>>>(ctx, wor, bo, out, 0, 1.0f);
}

// round 9
// speedup vs baseline: 3.3306x; 1.0684x over previous
#include <cuda_runtime.h>
#include <math.h>

#define BATCH 4
#define SEQ   2048
#define DM    1024
#define NH    16
#define HD    64
#define MROWS (BATCH * SEQ)   // 8192

__device__ float g_q[BATCH * NH * SEQ * HD];
__device__ float g_k[BATCH * NH * SEQ * HD];
__device__ float g_v[BATCH * NH * SEQ * HD];
__device__ float g_ctx[MROWS * DM];
__device__ float g_xr[MROWS * DM];      // tf32-rounded x
__device__ float g_wt[4][DM * DM];      // tf32-rounded TRANSPOSED weights [out][in]

// ---------------------------------------------------------------------------
// helpers
// ---------------------------------------------------------------------------
__device__ __forceinline__ unsigned f2tf32(float f) {
    unsigned u;
    asm("cvt.rna.tf32.f32 %0, %1;" : "=r"(u) : "f"(f));
    return u;
}

__device__ __forceinline__ void mma_tf32(float* d, const unsigned* a,
                                         unsigned b0, unsigned b1) {
    asm volatile(
        "mma.sync.aligned.m16n8k8.row.col.f32.tf32.tf32.f32 "
        "{%0,%1,%2,%3}, {%4,%5,%6,%7}, {%8,%9}, {%0,%1,%2,%3};\n"
        : "+f"(d[0]), "+f"(d[1]), "+f"(d[2]), "+f"(d[3])
        : "r"(a[0]), "r"(a[1]), "r"(a[2]), "r"(a[3]), "r"(b0), "r"(b1));
}

__device__ __forceinline__ unsigned saddr(const void* p) {
    return (unsigned)__cvta_generic_to_shared(p);
}
__device__ __forceinline__ void cp16(unsigned d, const void* s) {
    asm volatile("cp.async.cg.shared.global [%0], [%1], 16;" :: "r"(d), "l"(s));
}
#define CP_COMMIT asm volatile("cp.async.commit_group;")
#define CP_WAIT0  asm volatile("cp.async.wait_group 0;")

// ldmatrix x4 (b16): 4 8x8-b16 matrices == 2 8x8-b32 matrices split lo/hi cols
__device__ __forceinline__ void ldsm4(unsigned& r0, unsigned& r1,
                                      unsigned& r2, unsigned& r3, unsigned a) {
    asm volatile("ldmatrix.sync.aligned.m8n8.x4.shared.b16 {%0,%1,%2,%3}, [%4];"
                 : "=r"(r0), "=r"(r1), "=r"(r2), "=r"(r3) : "r"(a));
}

// ---------------------------------------------------------------------------
// preprocessing kernels
// ---------------------------------------------------------------------------
__global__ void round_tf32_k(const float* __restrict__ in,
                             float* __restrict__ out, int n4)
{
    int i = blockIdx.x * blockDim.x + threadIdx.x;
    if (i < n4) {
        float4 v = ((const float4*)in)[i];
        float4 o;
        o.x = __uint_as_float(f2tf32(v.x));
        o.y = __uint_as_float(f2tf32(v.y));
        o.z = __uint_as_float(f2tf32(v.z));
        o.w = __uint_as_float(f2tf32(v.w));
        ((float4*)out)[i] = o;
    }
}

// transpose 1024x1024 + tf32 round: out[n][k] = round(in[k][n])
__global__ void transpose_round_k(const float* __restrict__ in,
                                  float* __restrict__ out)
{
    __shared__ float t[32][33];
    int bx = blockIdx.x * 32, by = blockIdx.y * 32;
    int tx = threadIdx.x;
#pragma unroll
    for (int i = threadIdx.y; i < 32; i += 8)
        t[i][tx] = in[(size_t)(by + i) * DM + bx + tx];
    __syncthreads();
#pragma unroll
    for (int i = threadIdx.y; i < 32; i += 8)
        out[(size_t)(bx + i) * DM + by + tx] =
            __uint_as_float(f2tf32(t[tx][i]));
}

// ---------------------------------------------------------------------------
// tf32 GEMM, cp.async double-buffered, ldmatrix fragment loads.
// A: [m][k] tf32-rounded; Bt: [n][k] tf32-rounded (transposed weights).
// C = (A @ Bt^T + bias) * scale; qkv!=0 -> scatter [b,h,s,hd] + tf32 round.
// BM=BN=128, BK=32, 256 threads (8 warps, 4Mx2N), warp tile 32x64.
// smem: As[2][128][36], Bs[2][128][36]
// ---------------------------------------------------------------------------
#define G_STR 36
#define G_TILE (128 * G_STR)
#define G_SMEM (4 * G_TILE * 4)   // 73728 B

__device__ __forceinline__ void gemm_stage(
    const float* __restrict__ A, const float* __restrict__ Bt,
    unsigned Ab, unsigned Bb, int rowBase, int colBase, int k0, int tid)
{
#pragma unroll
    for (int it = 0; it < 4; it++) {
        int idx = tid + it * 256;       // 0..1023
        int r   = idx >> 3;             // 0..127
        int c4  = (idx & 7) * 4;        // 0..28
        cp16(Ab + (unsigned)(r * G_STR + c4) * 4,
             A  + (size_t)(rowBase + r) * DM + k0 + c4);
        cp16(Bb + (unsigned)(r * G_STR + c4) * 4,
             Bt + (size_t)(colBase + r) * DM + k0 + c4);
    }
}

__global__ __launch_bounds__(256, 2) void gemm_tf32_lm(
    const float* __restrict__ A, const float* __restrict__ Bt,
    const float* __restrict__ bias, float* __restrict__ C,
    int qkv, float scale)
{
    extern __shared__ float gsm[];
    const unsigned sA0 = saddr(gsm);
    const unsigned sB0 = sA0 + 2u * G_TILE * 4u;

    const int tid   = threadIdx.x;
    const int lane  = tid & 31;
    const int warp  = tid >> 5;
    const int warpM = warp & 3;
    const int warpN = warp >> 2;
    const int g     = lane >> 2;
    const int t     = lane & 3;
    const int rowBase = blockIdx.y * 128;
    const int colBase = blockIdx.x * 128;

    // ldmatrix per-lane base offsets (bytes): row = base+(lane&15), col=(lane>>4)*4
    const unsigned lmOff =
        ((unsigned)((lane & 15) * G_STR + (lane >> 4) * 4)) * 4u;
    const unsigned aOff = (unsigned)(warpM * 32 * G_STR) * 4u + lmOff;
    const unsigned bOff = (unsigned)(warpN * 64 * G_STR) * 4u + lmOff;

    float d[2][8][4];
#pragma unroll
    for (int mt = 0; mt < 2; mt++)
#pragma unroll
        for (int nt = 0; nt < 8; nt++)
#pragma unroll
            for (int j = 0; j < 4; j++) d[mt][nt][j] = 0.f;

    gemm_stage(A, Bt, sA0, sB0, rowBase, colBase, 0, tid);
    CP_COMMIT;

    for (int itn = 0; itn < 32; itn++) {
        const int buf = itn & 1;
        CP_WAIT0;
        __syncthreads();
        if (itn < 31) {
            gemm_stage(A, Bt, sA0 + (buf ^ 1) * G_TILE * 4,
                       sB0 + (buf ^ 1) * G_TILE * 4,
                       rowBase, colBase, (itn + 1) * 32, tid);
            CP_COMMIT;
        }
        const unsigned aB = sA0 + buf * G_TILE * 4 + aOff;
        const unsigned bB = sB0 + buf * G_TILE * 4 + bOff;

#pragma unroll
        for (int kk = 0; kk < 32; kk += 8) {
            unsigned a0[4], a1[4];
            ldsm4(a0[0], a0[1], a0[2], a0[3], aB + kk * 4);
            ldsm4(a1[0], a1[1], a1[2], a1[3], aB + (16 * G_STR + kk) * 4);
#pragma unroll
            for (int p = 0; p < 4; p++) {
                unsigned r0, r1, r2, r3;
                ldsm4(r0, r1, r2, r3, bB + (p * 16 * G_STR + kk) * 4);
                mma_tf32(d[0][2 * p],     a0, r0, r2);
                mma_tf32(d[0][2 * p + 1], a0, r1, r3);
                mma_tf32(d[1][2 * p],     a1, r0, r2);
                mma_tf32(d[1][2 * p + 1], a1, r1, r3);
            }
        }
    }

#pragma unroll
    for (int mt = 0; mt < 2; mt++) {
        int row0 = rowBase + warpM * 32 + mt * 16 + g;
#pragma unroll
        for (int nt = 0; nt < 8; nt++) {
            int col = colBase + warpN * 64 + nt * 8 + 2 * t;
            float bb0 = bias[col], bb1 = bias[col + 1];
            float v00 = (d[mt][nt][0] + bb0) * scale;
            float v01 = (d[mt][nt][1] + bb1) * scale;
            float v10 = (d[mt][nt][2] + bb0) * scale;
            float v11 = (d[mt][nt][3] + bb1) * scale;
            if (!qkv) {
                *(float2*)(C + (size_t)row0 * DM + col)       = make_float2(v00, v01);
                *(float2*)(C + (size_t)(row0 + 8) * DM + col) = make_float2(v10, v11);
            } else {
                v00 = __uint_as_float(f2tf32(v00));
                v01 = __uint_as_float(f2tf32(v01));
                v10 = __uint_as_float(f2tf32(v10));
                v11 = __uint_as_float(f2tf32(v11));
                int h = col >> 6, hd = col & 63;
                int b0i = row0 >> 11, s0 = row0 & 2047;
                int r1 = row0 + 8;
                int b1i = r1 >> 11, s1 = r1 & 2047;
                size_t base0 = (((size_t)(b0i * NH + h) * SEQ) + s0) * HD + hd;
                size_t base1 = (((size_t)(b1i * NH + h) * SEQ) + s1) * HD + hd;
                C[base0]     = v00;
                C[base0 + 1] = v01;
                C[base1]     = v10;
                C[base1 + 1] = v11;
            }
        }
    }
}

// ---------------------------------------------------------------------------
// Flash attention: tf32 mma, cp.async double-buffered K/V, ldmatrix Q/K frags,
// register-only P. Q pre-scaled by 1/sqrt(HD).
// Tile: 128 q x 64 k, 256 threads, warp = 16 q-rows x 64 keys.
// smem: Qs[128][68] | Ks[2][64][68] | Vs[2][64][72]
// ---------------------------------------------------------------------------
#define QS_STR 68
#define KS_STR 68
#define VS_STR 72
#define FA_SMEM ((128 * QS_STR + 2 * 64 * KS_STR + 2 * 64 * VS_STR) * 4)

__device__ __forceinline__ void fa_stage(
    const float* __restrict__ Kb, const float* __restrict__ Vb,
    unsigned Kd, unsigned Vd, int tid)
{
#pragma unroll
    for (int it = 0; it < 4; it++) {
        int idx = tid + it * 256;
        int r   = idx >> 4;
        int c4  = (idx & 15) * 4;
        cp16(Kd + (unsigned)(r * KS_STR + c4) * 4, Kb + r * HD + c4);
        cp16(Vd + (unsigned)(r * VS_STR + c4) * 4, Vb + r * HD + c4);
    }
}

__global__ __launch_bounds__(256, 2) void flash_attn_tc2(
    const float* __restrict__ Q, const float* __restrict__ K,
    const float* __restrict__ V, float* __restrict__ ctx)
{
    extern __shared__ float fsm[];
    float* Qs = fsm;
    float* Ks = fsm + 128 * QS_STR;
    float* Vs = fsm + 128 * QS_STR + 2 * 64 * KS_STR;
    const unsigned sQ = saddr(Qs);
    const unsigned sK = saddr(Ks);
    const unsigned sV = saddr(Vs);

    const int tid  = threadIdx.x;
    const int lane = tid & 31;
    const int warp = tid >> 5;
    const int g    = lane >> 2;
    const int t    = lane & 3;
    const int qt   = blockIdx.x;
    const int bh   = blockIdx.y;
    const int Q0   = qt * 128;
    const int rb   = warp * 16;

    const size_t base = (size_t)bh * SEQ * HD;

    // ldmatrix per-lane base offsets
    const unsigned qAddr = sQ +
        ((unsigned)((rb + (lane & 15)) * QS_STR + (lane >> 4) * 4)) * 4u;
    const unsigned kOff =
        ((unsigned)((lane & 15) * KS_STR + (lane >> 4) * 4)) * 4u;

    // prologue: stage Q and K/V tile 0
    {
        const float* Qb = Q + base + (size_t)Q0 * HD;
#pragma unroll
        for (int it = 0; it < 8; it++) {
            int idx = tid + it * 256;
            int r   = idx >> 4;
            int c4  = (idx & 15) * 4;
            cp16(sQ + (unsigned)(r * QS_STR + c4) * 4, Qb + r * HD + c4);
        }
        fa_stage(K + base, V + base, sK, sV, tid);
        CP_COMMIT;
    }

    float m[2] = {-INFINITY, -INFINITY};
    float l[2] = {0.f, 0.f};
    float O[8][4];
#pragma unroll
    for (int nf = 0; nf < 8; nf++)
#pragma unroll
        for (int j = 0; j < 4; j++) O[nf][j] = 0.f;

    int buf = 0;
    const int ktmax = 2 * qt + 1;
    for (int kt = 0; kt <= ktmax; kt++) {
        CP_WAIT0;
        __syncthreads();
        if (kt < ktmax) {
            fa_stage(K + base + (size_t)(kt + 1) * 64 * HD,
                     V + base + (size_t)(kt + 1) * 64 * HD,
                     sK + (unsigned)((buf ^ 1) * 64 * KS_STR) * 4,
                     sV + (unsigned)((buf ^ 1) * 64 * VS_STR) * 4, tid);
            CP_COMMIT;
        }
        const unsigned kB = sK + (unsigned)(buf * 64 * KS_STR) * 4 + kOff;
        const float* Vc = Vs + buf * 64 * VS_STR;

        // S = Q K^T  (ldmatrix fragments)
        float S[8][4];
#pragma unroll
        for (int nf = 0; nf < 8; nf++)
#pragma unroll
            for (int j = 0; j < 4; j++) S[nf][j] = 0.f;

#pragma unroll
        for (int kk = 0; kk < 8; kk++) {
            unsigned a[4];
            ldsm4(a[0], a[1], a[2], a[3], qAddr + kk * 32);
#pragma unroll
            for (int p = 0; p < 4; p++) {
                unsigned r0, r1, r2, r3;
                ldsm4(r0, r1, r2, r3, kB + (p * 16 * KS_STR) * 4 + kk * 32);
                mma_tf32(S[2 * p],     a, r0, r2);
                mma_tf32(S[2 * p + 1], a, r1, r3);
            }
        }

        if (kt >= 2 * qt) {   // causal mask (diagonal-adjacent tiles)
            int kb = kt * 64;
            int rlo = Q0 + rb + g, rhi = rlo + 8;
#pragma unroll
            for (int nf = 0; nf < 8; nf++) {
                int k0 = kb + nf * 8 + 2 * t;
                if (k0     > rlo) S[nf][0] = -INFINITY;
                if (k0 + 1 > rlo) S[nf][1] = -INFINITY;
                if (k0     > rhi) S[nf][2] = -INFINITY;
                if (k0 + 1 > rhi) S[nf][3] = -INFINITY;
            }
        }

        // online softmax
#pragma unroll
        for (int h2 = 0; h2 < 2; h2++) {
            float mx = -INFINITY;
#pragma unroll
            for (int nf = 0; nf < 8; nf++)
                mx = fmaxf(mx, fmaxf(S[nf][2 * h2], S[nf][2 * h2 + 1]));
            mx = fmaxf(mx, __shfl_xor_sync(0xffffffffu, mx, 1));
            mx = fmaxf(mx, __shfl_xor_sync(0xffffffffu, mx, 2));
            float mn = fmaxf(m[h2], mx);
            float sc = __expf(m[h2] - mn);
            m[h2] = mn;
            float rs = 0.f;
#pragma unroll
            for (int nf = 0; nf < 8; nf++) {
                float e0 = __expf(S[nf][2 * h2]     - mn);
                float e1 = __expf(S[nf][2 * h2 + 1] - mn);
                S[nf][2 * h2] = e0; S[nf][2 * h2 + 1] = e1;
                rs += e0 + e1;
            }
            rs += __shfl_xor_sync(0xffffffffu, rs, 1);
            rs += __shfl_xor_sync(0xffffffffu, rs, 2);
            l[h2] = l[h2] * sc + rs;
#pragma unroll
            for (int nf = 0; nf < 8; nf++) {
                O[nf][2 * h2]     *= sc;
                O[nf][2 * h2 + 1] *= sc;
            }
        }

        // O += P V  — P converted C-frag -> A-frag via quad shuffles
        {
            const int srcA = (lane & 28) | (t >> 1);
            const int srcB = srcA + 2;
            const bool odd = (t & 1);
#pragma unroll
            for (int kk = 0; kk < 8; kk++) {
                float s0A = __shfl_sync(0xffffffffu, S[kk][0], srcA);
                float s1A = __shfl_sync(0xffffffffu, S[kk][1], srcA);
                float s2A = __shfl_sync(0xffffffffu, S[kk][2], srcA);
                float s3A = __shfl_sync(0xffffffffu, S[kk][3], srcA);
                float s0B = __shfl_sync(0xffffffffu, S[kk][0], srcB);
                float s1B = __shfl_sync(0xffffffffu, S[kk][1], srcB);
                float s2B = __shfl_sync(0xffffffffu, S[kk][2], srcB);
                float s3B = __shfl_sync(0xffffffffu, S[kk][3], srcB);
                unsigned a[4];
                a[0] = f2tf32(odd ? s1A : s0A);
                a[1] = f2tf32(odd ? s3A : s2A);
                a[2] = f2tf32(odd ? s1B : s0B);
                a[3] = f2tf32(odd ? s3B : s2B);
#pragma unroll
                for (int nf = 0; nf < 8; nf++) {
                    unsigned b0 = __float_as_uint(Vc[(kk * 8 + t    ) * VS_STR + nf * 8 + g]);
                    unsigned b1 = __float_as_uint(Vc[(kk * 8 + t + 4) * VS_STR + nf * 8 + g]);
                    mma_tf32(O[nf], a, b0, b1);
                }
            }
        }
        buf ^= 1;
    }

    // epilogue
    const int b = bh >> 4, hh = bh & 15;
#pragma unroll
    for (int h2 = 0; h2 < 2; h2++) {
        float inv = 1.f / l[h2];
        int row = Q0 + rb + g + 8 * h2;
        float* dst = ctx + ((size_t)(b * SEQ + row)) * DM + hh * HD;
#pragma unroll
        for (int nf = 0; nf < 8; nf++) {
            int c = nf * 8 + 2 * t;
            float o0 = __uint_as_float(f2tf32(O[nf][2 * h2]     * inv));
            float o1 = __uint_as_float(f2tf32(O[nf][2 * h2 + 1] * inv));
            *(float2*)(dst + c) = make_float2(o0, o1);
        }
    }
}

// ---------------------------------------------------------------------------
// Launch
// ---------------------------------------------------------------------------
extern "C" void kernel_launch(void* const* d_in, const int* in_sizes, int n_in,
                              void* d_out, int out_size)
{
    const float* x  = (const float*)d_in[0];
    const float* wq = (const float*)d_in[1];
    const float* bq = (const float*)d_in[2];
    const float* wk = (const float*)d_in[3];
    const float* bk = (const float*)d_in[4];
    const float* wv = (const float*)d_in[5];
    const float* bv = (const float*)d_in[6];
    const float* wo = (const float*)d_in[7];
    const float* bo = (const float*)d_in[8];
    float* out = (float*)d_out;

    float *q, *k, *v, *ctx, *xr, *wt;
    cudaGetSymbolAddress((void**)&q,   g_q);
    cudaGetSymbolAddress((void**)&k,   g_k);
    cudaGetSymbolAddress((void**)&v,   g_v);
    cudaGetSymbolAddress((void**)&ctx, g_ctx);
    cudaGetSymbolAddress((void**)&xr,  g_xr);
    cudaGetSymbolAddress((void**)&wt,  g_wt);
    float* wqT = wt;
    float* wkT = wt + DM * DM;
    float* wvT = wt + 2 * DM * DM;
    float* woT = wt + 3 * DM * DM;

    cudaFuncSetAttribute(gemm_tf32_lm,
                         cudaFuncAttributeMaxDynamicSharedMemorySize, G_SMEM);
    cudaFuncSetAttribute(flash_attn_tc2,
                         cudaFuncAttributeMaxDynamicSharedMemorySize, FA_SMEM);

    // preprocess: round x; transpose+round weights
    {
        int n4x = MROWS * DM / 4;
        round_tf32_k<<<(n4x + 255) / 256, 256>>>(x, xr, n4x);
        dim3 tb(32, 8), tg(32, 32);
        transpose_round_k<<<tg, tb>>>(wq, wqT);
        transpose_round_k<<<tg, tb>>>(wk, wkT);
        transpose_round_k<<<tg, tb>>>(wv, wvT);
        transpose_round_k<<<tg, tb>>>(wo, woT);
    }

    dim3 gg(DM / 128, MROWS / 128);   // (8, 64)
    const float qscale = 0.125f;      // 1/sqrt(64)

    gemm_tf32_lm<<<gg, 256, G_SMEM>>>(xr, wqT, bq, q, 1, qscale);
    gemm_tf32_lm<<<gg, 256, G_SMEM>>>(xr, wkT, bk, k, 1, 1.0f);
    gemm_tf32_lm<<<gg, 256, G_SMEM>>>(xr, wvT, bv, v, 1, 1.0f);

    flash_attn_tc2<<<dim3(SEQ / 128, BATCH * NH), 256, FA_SMEM>>>(q, k, v, ctx);

    gemm_tf32_lm<<<gg, 256, G_SMEM>>>(ctx, woT, bo, out, 0, 1.0f);
}

// round 10
// speedup vs baseline: 7.1052x; 2.1333x over previous
#include <cuda_runtime.h>
#include <cuda_fp16.h>
#include <math.h>

#define BATCH 4
#define SEQ   2048
#define DM    1024
#define NH    16
#define HD    64
#define MROWS (BATCH * SEQ)   // 8192

__device__ __half g_qkv[3][BATCH * NH * SEQ * HD];
__device__ __half g_ctx[MROWS * DM];
__device__ __half g_xh[MROWS * DM];        // fp16 x
__device__ __half g_wth[4][DM * DM];       // fp16 TRANSPOSED weights [out][in]

// ---------------------------------------------------------------------------
// helpers
// ---------------------------------------------------------------------------
__device__ __forceinline__ unsigned h2pack(float a, float b) {
    __half2 h = __floats2half2_rn(a, b);
    return *(unsigned*)&h;
}

__device__ __forceinline__ void mma_fp16(float* d, const unsigned* a,
                                         unsigned b0, unsigned b1) {
    asm volatile(
        "mma.sync.aligned.m16n8k16.row.col.f32.f16.f16.f32 "
        "{%0,%1,%2,%3}, {%4,%5,%6,%7}, {%8,%9}, {%0,%1,%2,%3};\n"
        : "+f"(d[0]), "+f"(d[1]), "+f"(d[2]), "+f"(d[3])
        : "r"(a[0]), "r"(a[1]), "r"(a[2]), "r"(a[3]), "r"(b0), "r"(b1));
}

__device__ __forceinline__ unsigned saddr(const void* p) {
    return (unsigned)__cvta_generic_to_shared(p);
}
__device__ __forceinline__ void cp16(unsigned d, const void* s) {
    asm volatile("cp.async.cg.shared.global [%0], [%1], 16;" :: "r"(d), "l"(s));
}
#define CP_COMMIT asm volatile("cp.async.commit_group;")
#define CP_WAIT0  asm volatile("cp.async.wait_group 0;")

__device__ __forceinline__ void ldsm4(unsigned& r0, unsigned& r1,
                                      unsigned& r2, unsigned& r3, unsigned a) {
    asm volatile("ldmatrix.sync.aligned.m8n8.x4.shared.b16 {%0,%1,%2,%3}, [%4];"
                 : "=r"(r0), "=r"(r1), "=r"(r2), "=r"(r3) : "r"(a));
}
__device__ __forceinline__ void ldsm4t(unsigned& r0, unsigned& r1,
                                       unsigned& r2, unsigned& r3, unsigned a) {
    asm volatile("ldmatrix.sync.aligned.m8n8.x4.trans.shared.b16 {%0,%1,%2,%3}, [%4];"
                 : "=r"(r0), "=r"(r1), "=r"(r2), "=r"(r3) : "r"(a));
}

// ---------------------------------------------------------------------------
// preprocessing: x -> fp16; weights -> transposed fp16 (all 4 in one launch)
// ---------------------------------------------------------------------------
__global__ void round_fp16_k(const float* __restrict__ in,
                             __half* __restrict__ out, int n4)
{
    int i = blockIdx.x * blockDim.x + threadIdx.x;
    if (i < n4) {
        float4 v = ((const float4*)in)[i];
        __half2* o = (__half2*)(out + i * 4);
        o[0] = __floats2half2_rn(v.x, v.y);
        o[1] = __floats2half2_rn(v.z, v.w);
    }
}

__global__ void transpose_fp16_k(const float* __restrict__ w0,
                                 const float* __restrict__ w1,
                                 const float* __restrict__ w2,
                                 const float* __restrict__ w3,
                                 __half* __restrict__ out)
{
    __shared__ float t[32][33];
    const float* in = (blockIdx.z == 0) ? w0 : (blockIdx.z == 1) ? w1
                    : (blockIdx.z == 2) ? w2 : w3;
    __half* o = out + (size_t)blockIdx.z * DM * DM;
    int bx = blockIdx.x * 32, by = blockIdx.y * 32;
    int tx = threadIdx.x;
#pragma unroll
    for (int i = threadIdx.y; i < 32; i += 8)
        t[i][tx] = in[(size_t)(by + i) * DM + bx + tx];
    __syncthreads();
#pragma unroll
    for (int i = threadIdx.y; i < 32; i += 8)
        o[(size_t)(bx + i) * DM + by + tx] = __float2half_rn(t[tx][i]);
}

// ---------------------------------------------------------------------------
// fp16 GEMM core: C = (A[M,1024] @ Bt^T + bias) * scale
// A fp16 [m][k]; Bt fp16 [n][k]. BM=BN=128, BK=64 halves, 2-stage cp.async.
// 8 warps (4M x 2N), warp tile 32x64, m16n8k16.
// smem stride 72 halves (144 B) -> ldmatrix conflict-free.
// ---------------------------------------------------------------------------
#define G_STR 72                      // halves
#define G_TILE_B (128 * G_STR * 2)    // 18432 bytes per tile
#define G_SMEM (4 * G_TILE_B)         // 73728 B (A0,A1,B0,B1)

__device__ __forceinline__ void gemm_stage(
    const __half* __restrict__ A, const __half* __restrict__ Bt,
    unsigned Ab, unsigned Bb, int rowBase, int colBase, int k0, int tid)
{
#pragma unroll
    for (int it = 0; it < 4; it++) {
        int idx = tid + it * 256;       // 0..1023
        int r   = idx >> 3;             // 0..127
        int c8  = (idx & 7) * 8;        // 0..56 halves
        cp16(Ab + (unsigned)(r * G_STR + c8) * 2,
             A  + (size_t)(rowBase + r) * DM + k0 + c8);
        cp16(Bb + (unsigned)(r * G_STR + c8) * 2,
             Bt + (size_t)(colBase + r) * DM + k0 + c8);
    }
}

struct GemmOut {
    float d[2][8][4];
};

__device__ __forceinline__ void gemm_core(
    const __half* A, const __half* Bt, unsigned sA0, unsigned sB0,
    int rowBase, int colBase, int tid, int lane, int warpM, int warpN,
    GemmOut& o)
{
#pragma unroll
    for (int mt = 0; mt < 2; mt++)
#pragma unroll
        for (int nt = 0; nt < 8; nt++)
#pragma unroll
            for (int j = 0; j < 4; j++) o.d[mt][nt][j] = 0.f;

    // ldmatrix per-lane offsets (bytes)
    // A frag: row = base + (lane&15), koff(halves) = (lane>>4)*8
    const unsigned aOff =
        ((unsigned)((warpM * 32 + (lane & 15)) * G_STR + (lane >> 4) * 8)) * 2u;
    // B frag: row = base + (lane&7) + ((lane>>4)&1)*8, koff = ((lane>>3)&1)*8
    const unsigned bOff =
        ((unsigned)((warpN * 64 + (lane & 7) + ((lane >> 4) & 1) * 8) * G_STR
                    + ((lane >> 3) & 1) * 8)) * 2u;

    gemm_stage(A, Bt, sA0, sB0, rowBase, colBase, 0, tid);
    CP_COMMIT;

    for (int itn = 0; itn < 16; itn++) {
        const int buf = itn & 1;
        CP_WAIT0;
        __syncthreads();
        if (itn < 15) {
            gemm_stage(A, Bt, sA0 + (buf ^ 1) * G_TILE_B,
                       sB0 + (buf ^ 1) * G_TILE_B,
                       rowBase, colBase, (itn + 1) * 64, tid);
            CP_COMMIT;
        }
        const unsigned aB = sA0 + buf * G_TILE_B + aOff;
        const unsigned bB = sB0 + buf * G_TILE_B + bOff;

#pragma unroll
        for (int kk = 0; kk < 4; kk++) {     // 4 x k16
            unsigned a0[4], a1[4];
            ldsm4(a0[0], a0[1], a0[2], a0[3], aB + kk * 32);
            ldsm4(a1[0], a1[1], a1[2], a1[3], aB + 16 * G_STR * 2 + kk * 32);
#pragma unroll
            for (int p = 0; p < 4; p++) {    // 4 x (2 n-groups)
                unsigned r0, r1, r2, r3;
                ldsm4(r0, r1, r2, r3, bB + p * 16 * G_STR * 2 + kk * 32);
                mma_fp16(o.d[0][2 * p],     a0, r0, r1);
                mma_fp16(o.d[0][2 * p + 1], a0, r2, r3);
                mma_fp16(o.d[1][2 * p],     a1, r0, r1);
                mma_fp16(o.d[1][2 * p + 1], a1, r2, r3);
            }
        }
    }
}

// QKV GEMM: grid.z selects q/k/v; scatter fp16 to [b,h,s,hd]
__global__ __launch_bounds__(256, 2) void gemm_qkv(
    const __half* __restrict__ A, const __half* __restrict__ WtBase,
    const float* __restrict__ bq, const float* __restrict__ bk,
    const float* __restrict__ bv, __half* __restrict__ Obase)
{
    extern __shared__ __half gsm[];
    const unsigned sA0 = saddr(gsm);
    const unsigned sB0 = sA0 + 2u * G_TILE_B;

    const int z = blockIdx.z;
    const __half* Bt = WtBase + (size_t)z * DM * DM;
    const float* bias = (z == 0) ? bq : (z == 1) ? bk : bv;
    __half* C = Obase + (size_t)z * (BATCH * NH * SEQ * HD);
    const float scale = (z == 0) ? 0.125f : 1.0f;

    const int tid   = threadIdx.x;
    const int lane  = tid & 31;
    const int warp  = tid >> 5;
    const int warpM = warp & 3;
    const int warpN = warp >> 2;
    const int g     = lane >> 2;
    const int t     = lane & 3;
    const int rowBase = blockIdx.y * 128;
    const int colBase = blockIdx.x * 128;

    GemmOut o;
    gemm_core(A, Bt, sA0, sB0, rowBase, colBase, tid, lane, warpM, warpN, o);

#pragma unroll
    for (int mt = 0; mt < 2; mt++) {
        int row0 = rowBase + warpM * 32 + mt * 16 + g;
#pragma unroll
        for (int nt = 0; nt < 8; nt++) {
            int col = colBase + warpN * 64 + nt * 8 + 2 * t;
            float bb0 = bias[col], bb1 = bias[col + 1];
            unsigned v0 = h2pack((o.d[mt][nt][0] + bb0) * scale,
                                 (o.d[mt][nt][1] + bb1) * scale);
            unsigned v1 = h2pack((o.d[mt][nt][2] + bb0) * scale,
                                 (o.d[mt][nt][3] + bb1) * scale);
            int h = col >> 6, hd = col & 63;
            int b0i = row0 >> 11, s0 = row0 & 2047;
            int r1 = row0 + 8;
            int b1i = r1 >> 11, s1 = r1 & 2047;
            *(unsigned*)(C + (((size_t)(b0i * NH + h) * SEQ) + s0) * HD + hd) = v0;
            *(unsigned*)(C + (((size_t)(b1i * NH + h) * SEQ) + s1) * HD + hd) = v1;
        }
    }
}

// Output GEMM: fp32 plain row-major out
__global__ __launch_bounds__(256, 2) void gemm_out(
    const __half* __restrict__ A, const __half* __restrict__ Bt,
    const float* __restrict__ bias, float* __restrict__ C)
{
    extern __shared__ __half gsm[];
    const unsigned sA0 = saddr(gsm);
    const unsigned sB0 = sA0 + 2u * G_TILE_B;

    const int tid   = threadIdx.x;
    const int lane  = tid & 31;
    const int warp  = tid >> 5;
    const int warpM = warp & 3;
    const int warpN = warp >> 2;
    const int g     = lane >> 2;
    const int t     = lane & 3;
    const int rowBase = blockIdx.y * 128;
    const int colBase = blockIdx.x * 128;

    GemmOut o;
    gemm_core(A, Bt, sA0, sB0, rowBase, colBase, tid, lane, warpM, warpN, o);

#pragma unroll
    for (int mt = 0; mt < 2; mt++) {
        int row0 = rowBase + warpM * 32 + mt * 16 + g;
#pragma unroll
        for (int nt = 0; nt < 8; nt++) {
            int col = colBase + warpN * 64 + nt * 8 + 2 * t;
            float bb0 = bias[col], bb1 = bias[col + 1];
            *(float2*)(C + (size_t)row0 * DM + col) =
                make_float2(o.d[mt][nt][0] + bb0, o.d[mt][nt][1] + bb1);
            *(float2*)(C + (size_t)(row0 + 8) * DM + col) =
                make_float2(o.d[mt][nt][2] + bb0, o.d[mt][nt][3] + bb1);
        }
    }
}

// ---------------------------------------------------------------------------
// Flash attention fp16: m16n8k16, cp.async double-buffered K/V,
// ldmatrix Q/K frags, ldmatrix.trans V frags, register-packed P.
// Tile: 128 q x 64 k, 256 threads, warp = 16 q-rows x 64 keys.
// smem: Qs[128][72h] | Ks[2][64][72h] | Vs[2][64][72h]  (55296 B)
// ---------------------------------------------------------------------------
#define F_STR 72
#define FQ_B (128 * F_STR * 2)     // 18432
#define FK_B (64 * F_STR * 2)      // 9216
#define FA_SMEM (FQ_B + 4 * FK_B)  // 55296

__device__ __forceinline__ void fa_stage(
    const __half* __restrict__ Kb, const __half* __restrict__ Vb,
    unsigned Kd, unsigned Vd, int tid)
{
#pragma unroll
    for (int it = 0; it < 2; it++) {
        int idx = tid + it * 256;       // 0..511
        int r   = idx >> 3;             // 0..63
        int c8  = (idx & 7) * 8;
        cp16(Kd + (unsigned)(r * F_STR + c8) * 2, Kb + r * HD + c8);
        cp16(Vd + (unsigned)(r * F_STR + c8) * 2, Vb + r * HD + c8);
    }
}

__global__ __launch_bounds__(256, 2) void flash_fp16(
    const __half* __restrict__ Q, const __half* __restrict__ K,
    const __half* __restrict__ V, __half* __restrict__ ctx)
{
    extern __shared__ __half fsm[];
    const unsigned sQ = saddr(fsm);
    const unsigned sK = sQ + FQ_B;
    const unsigned sV = sK + 2 * FK_B;

    const int tid  = threadIdx.x;
    const int lane = tid & 31;
    const int warp = tid >> 5;
    const int g    = lane >> 2;
    const int t    = lane & 3;
    const int qt   = blockIdx.x;
    const int bh   = blockIdx.y;
    const int Q0   = qt * 128;
    const int rb   = warp * 16;

    const size_t base = (size_t)bh * SEQ * HD;

    // per-lane ldmatrix offsets (bytes)
    const unsigned qAddr = sQ +
        ((unsigned)((rb + (lane & 15)) * F_STR + (lane >> 4) * 8)) * 2u;
    const unsigned kOff =
        ((unsigned)(((lane & 7) + ((lane >> 4) & 1) * 8) * F_STR
                    + ((lane >> 3) & 1) * 8)) * 2u;
    const unsigned vOff =
        ((unsigned)(((lane & 7) + ((lane >> 3) & 1) * 8) * F_STR
                    + (lane >> 4) * 8)) * 2u;

    // prologue: stage Q + K/V tile 0
    {
        const __half* Qb = Q + base + (size_t)Q0 * HD;
#pragma unroll
        for (int it = 0; it < 4; it++) {
            int idx = tid + it * 256;   // 0..1023
            int r   = idx >> 3;         // 0..127
            int c8  = (idx & 7) * 8;
            cp16(sQ + (unsigned)(r * F_STR + c8) * 2, Qb + r * HD + c8);
        }
        fa_stage(K + base, V + base, sK, sV, tid);
        CP_COMMIT;
    }

    float m[2] = {-INFINITY, -INFINITY};
    float l[2] = {0.f, 0.f};
    float O[8][4];
#pragma unroll
    for (int nf = 0; nf < 8; nf++)
#pragma unroll
        for (int j = 0; j < 4; j++) O[nf][j] = 0.f;

    int buf = 0;
    const int ktmax = 2 * qt + 1;
    for (int kt = 0; kt <= ktmax; kt++) {
        CP_WAIT0;
        __syncthreads();
        if (kt < ktmax) {
            fa_stage(K + base + (size_t)(kt + 1) * 64 * HD,
                     V + base + (size_t)(kt + 1) * 64 * HD,
                     sK + (buf ^ 1) * FK_B, sV + (buf ^ 1) * FK_B, tid);
            CP_COMMIT;
        }
        const unsigned kB = sK + buf * FK_B + kOff;
        const unsigned vB = sV + buf * FK_B + vOff;

        // S = Q K^T
        float S[8][4];
#pragma unroll
        for (int nf = 0; nf < 8; nf++)
#pragma unroll
            for (int j = 0; j < 4; j++) S[nf][j] = 0.f;

#pragma unroll
        for (int kk = 0; kk < 4; kk++) {     // 4 x k16 over d=64
            unsigned a[4];
            ldsm4(a[0], a[1], a[2], a[3], qAddr + kk * 32);
#pragma unroll
            for (int p = 0; p < 4; p++) {    // keys: 2 n-groups per ldsm4
                unsigned r0, r1, r2, r3;
                ldsm4(r0, r1, r2, r3, kB + p * 16 * F_STR * 2 + kk * 32);
                mma_fp16(S[2 * p],     a, r0, r1);
                mma_fp16(S[2 * p + 1], a, r2, r3);
            }
        }

        if (kt >= 2 * qt) {   // causal mask (diagonal-adjacent tiles)
            int kb = kt * 64;
            int rlo = Q0 + rb + g, rhi = rlo + 8;
#pragma unroll
            for (int nf = 0; nf < 8; nf++) {
                int k0 = kb + nf * 8 + 2 * t;
                if (k0     > rlo) S[nf][0] = -INFINITY;
                if (k0 + 1 > rlo) S[nf][1] = -INFINITY;
                if (k0     > rhi) S[nf][2] = -INFINITY;
                if (k0 + 1 > rhi) S[nf][3] = -INFINITY;
            }
        }

        // online softmax
#pragma unroll
        for (int h2 = 0; h2 < 2; h2++) {
            float mx = -INFINITY;
#pragma unroll
            for (int nf = 0; nf < 8; nf++)
                mx = fmaxf(mx, fmaxf(S[nf][2 * h2], S[nf][2 * h2 + 1]));
            mx = fmaxf(mx, __shfl_xor_sync(0xffffffffu, mx, 1));
            mx = fmaxf(mx, __shfl_xor_sync(0xffffffffu, mx, 2));
            float mn = fmaxf(m[h2], mx);
            float sc = __expf(m[h2] - mn);
            m[h2] = mn;
            float rs = 0.f;
#pragma unroll
            for (int nf = 0; nf < 8; nf++) {
                float e0 = __expf(S[nf][2 * h2]     - mn);
                float e1 = __expf(S[nf][2 * h2 + 1] - mn);
                S[nf][2 * h2] = e0; S[nf][2 * h2 + 1] = e1;
                rs += e0 + e1;
            }
            rs += __shfl_xor_sync(0xffffffffu, rs, 1);
            rs += __shfl_xor_sync(0xffffffffu, rs, 2);
            l[h2] = l[h2] * sc + rs;
#pragma unroll
            for (int nf = 0; nf < 8; nf++) {
                O[nf][2 * h2]     *= sc;
                O[nf][2 * h2 + 1] *= sc;
            }
        }

        // O += P V  — P packs directly into fp16 A-frags (no shuffles)
#pragma unroll
        for (int mkey = 0; mkey < 4; mkey++) {   // key16 groups
            unsigned a[4];
            a[0] = h2pack(S[2 * mkey][0],     S[2 * mkey][1]);
            a[1] = h2pack(S[2 * mkey][2],     S[2 * mkey][3]);
            a[2] = h2pack(S[2 * mkey + 1][0], S[2 * mkey + 1][1]);
            a[3] = h2pack(S[2 * mkey + 1][2], S[2 * mkey + 1][3]);
#pragma unroll
            for (int p = 0; p < 4; p++) {        // d: 2 n-groups per ldsm4t
                unsigned r0, r1, r2, r3;
                ldsm4t(r0, r1, r2, r3,
                       vB + (mkey * 16 * F_STR + p * 16) * 2);
                mma_fp16(O[2 * p],     a, r0, r1);
                mma_fp16(O[2 * p + 1], a, r2, r3);
            }
        }
        buf ^= 1;
    }

    // epilogue: normalize, fp16, write ctx [b*SEQ + q][h*64 + d]
    const int b = bh >> 4, hh = bh & 15;
#pragma unroll
    for (int h2 = 0; h2 < 2; h2++) {
        float inv = 1.f / l[h2];
        int row = Q0 + rb + g + 8 * h2;
        __half* dst = ctx + ((size_t)(b * SEQ + row)) * DM + hh * HD;
#pragma unroll
        for (int nf = 0; nf < 8; nf++) {
            int c = nf * 8 + 2 * t;
            *(unsigned*)(dst + c) =
                h2pack(O[nf][2 * h2] * inv, O[nf][2 * h2 + 1] * inv);
        }
    }
}

// ---------------------------------------------------------------------------
// Launch
// ---------------------------------------------------------------------------
extern "C" void kernel_launch(void* const* d_in, const int* in_sizes, int n_in,
                              void* d_out, int out_size)
{
    const float* x  = (const float*)d_in[0];
    const float* wq = (const float*)d_in[1];
    const float* bq = (const float*)d_in[2];
    const float* wk = (const float*)d_in[3];
    const float* bk = (const float*)d_in[4];
    const float* wv = (const float*)d_in[5];
    const float* bv = (const float*)d_in[6];
    const float* wo = (const float*)d_in[7];
    const float* bo = (const float*)d_in[8];
    float* out = (float*)d_out;

    __half *qkv, *ctx, *xh, *wth;
    cudaGetSymbolAddress((void**)&qkv, g_qkv);
    cudaGetSymbolAddress((void**)&ctx, g_ctx);
    cudaGetSymbolAddress((void**)&xh,  g_xh);
    cudaGetSymbolAddress((void**)&wth, g_wth);
    const size_t HSZ = (size_t)BATCH * NH * SEQ * HD;

    cudaFuncSetAttribute(gemm_qkv,
                         cudaFuncAttributeMaxDynamicSharedMemorySize, G_SMEM);
    cudaFuncSetAttribute(gemm_out,
                         cudaFuncAttributeMaxDynamicSharedMemorySize, G_SMEM);
    cudaFuncSetAttribute(flash_fp16,
                         cudaFuncAttributeMaxDynamicSharedMemorySize, FA_SMEM);

    // preprocess
    {
        int n4x = MROWS * DM / 4;
        round_fp16_k<<<(n4x + 255) / 256, 256>>>(x, xh, n4x);
        transpose_fp16_k<<<dim3(32, 32, 4), dim3(32, 8)>>>(wq, wk, wv, wo, wth);
    }

    // QKV (merged), flash, output projection
    gemm_qkv<<<dim3(DM / 128, MROWS / 128, 3), 256, G_SMEM>>>(
        xh, wth, bq, bk, bv, qkv);

    flash_fp16<<<dim3(SEQ / 128, BATCH * NH), 256, FA_SMEM>>>(
        qkv, qkv + HSZ, qkv + 2 * HSZ, ctx);

    gemm_out<<<dim3(DM / 128, MROWS / 128), 256, G_SMEM>>>(
        ctx, wth + 3 * (size_t)DM * DM, bo, out);
}

// round 11
// speedup vs baseline: 7.3382x; 1.0328x over previous
#include <cuda_runtime.h>
#include <cuda_fp16.h>
#include <math.h>

#define BATCH 4
#define SEQ   2048
#define DM    1024
#define NH    16
#define HD    64
#define MROWS (BATCH * SEQ)   // 8192

__device__ __half g_qkv[3][BATCH * NH * SEQ * HD];
__device__ __half g_ctx[MROWS * DM];
__device__ __half g_xh[MROWS * DM];
__device__ __half g_wth[4][DM * DM];       // fp16 TRANSPOSED weights [out][in]

// ---------------------------------------------------------------------------
// helpers
// ---------------------------------------------------------------------------
__device__ __forceinline__ unsigned h2pack(float a, float b) {
    __half2 h = __floats2half2_rn(a, b);
    return *(unsigned*)&h;
}

__device__ __forceinline__ void mma_fp16(float* d, const unsigned* a,
                                         unsigned b0, unsigned b1) {
    asm volatile(
        "mma.sync.aligned.m16n8k16.row.col.f32.f16.f16.f32 "
        "{%0,%1,%2,%3}, {%4,%5,%6,%7}, {%8,%9}, {%0,%1,%2,%3};\n"
        : "+f"(d[0]), "+f"(d[1]), "+f"(d[2]), "+f"(d[3])
        : "r"(a[0]), "r"(a[1]), "r"(a[2]), "r"(a[3]), "r"(b0), "r"(b1));
}

__device__ __forceinline__ unsigned saddr(const void* p) {
    return (unsigned)__cvta_generic_to_shared(p);
}
__device__ __forceinline__ void cp16(unsigned d, const void* s) {
    asm volatile("cp.async.cg.shared.global [%0], [%1], 16;" :: "r"(d), "l"(s));
}
#define CP_COMMIT asm volatile("cp.async.commit_group;")
#define CP_WAIT0  asm volatile("cp.async.wait_group 0;")
#define CP_WAIT1  asm volatile("cp.async.wait_group 1;")

__device__ __forceinline__ void ldsm4(unsigned& r0, unsigned& r1,
                                      unsigned& r2, unsigned& r3, unsigned a) {
    asm volatile("ldmatrix.sync.aligned.m8n8.x4.shared.b16 {%0,%1,%2,%3}, [%4];"
                 : "=r"(r0), "=r"(r1), "=r"(r2), "=r"(r3) : "r"(a));
}
__device__ __forceinline__ void ldsm4t(unsigned& r0, unsigned& r1,
                                       unsigned& r2, unsigned& r3, unsigned a) {
    asm volatile("ldmatrix.sync.aligned.m8n8.x4.trans.shared.b16 {%0,%1,%2,%3}, [%4];"
                 : "=r"(r0), "=r"(r1), "=r"(r2), "=r"(r3) : "r"(a));
}

// ---------------------------------------------------------------------------
// preprocessing
// ---------------------------------------------------------------------------
__global__ void round_fp16_k(const float* __restrict__ in,
                             __half* __restrict__ out, int n4)
{
    int i = blockIdx.x * blockDim.x + threadIdx.x;
    if (i < n4) {
        float4 v = ((const float4*)in)[i];
        __half2* o = (__half2*)(out + i * 4);
        o[0] = __floats2half2_rn(v.x, v.y);
        o[1] = __floats2half2_rn(v.z, v.w);
    }
}

__global__ void transpose_fp16_k(const float* __restrict__ w0,
                                 const float* __restrict__ w1,
                                 const float* __restrict__ w2,
                                 const float* __restrict__ w3,
                                 __half* __restrict__ out)
{
    __shared__ float t[32][33];
    const float* in = (blockIdx.z == 0) ? w0 : (blockIdx.z == 1) ? w1
                    : (blockIdx.z == 2) ? w2 : w3;
    __half* o = out + (size_t)blockIdx.z * DM * DM;
    int bx = blockIdx.x * 32, by = blockIdx.y * 32;
    int tx = threadIdx.x;
#pragma unroll
    for (int i = threadIdx.y; i < 32; i += 8)
        t[i][tx] = in[(size_t)(by + i) * DM + bx + tx];
    __syncthreads();
#pragma unroll
    for (int i = threadIdx.y; i < 32; i += 8)
        o[(size_t)(bx + i) * DM + by + tx] = __float2half_rn(t[tx][i]);
}

// ---------------------------------------------------------------------------
// fp16 GEMM core, 3-stage cp.async ring. BM=BN=128, BK=64 halves,
// 256 threads (8 warps, 4M x 2N), warp tile 32x64, m16n8k16.
// ---------------------------------------------------------------------------
#define G_STR 72
#define G_TILE_B (128 * G_STR * 2)        // 18432 B (one operand tile)
#define G_STAGE_B (2 * G_TILE_B)          // 36864 B (A+B)
#define G_SMEM (3 * G_STAGE_B)            // 110592 B

__device__ __forceinline__ void gemm_stage(
    const __half* __restrict__ A, const __half* __restrict__ Bt,
    unsigned stageBase, int rowBase, int colBase, int k0, int tid)
{
    unsigned Ab = stageBase;
    unsigned Bb = stageBase + G_TILE_B;
#pragma unroll
    for (int it = 0; it < 4; it++) {
        int idx = tid + it * 256;       // 0..1023
        int r   = idx >> 3;             // 0..127
        int c8  = (idx & 7) * 8;        // 0..56 halves
        cp16(Ab + (unsigned)(r * G_STR + c8) * 2,
             A  + (size_t)(rowBase + r) * DM + k0 + c8);
        cp16(Bb + (unsigned)(r * G_STR + c8) * 2,
             Bt + (size_t)(colBase + r) * DM + k0 + c8);
    }
}

struct GemmOut {
    float d[2][8][4];
};

__device__ __forceinline__ void gemm_core(
    const __half* A, const __half* Bt, unsigned s0,
    int rowBase, int colBase, int tid, int lane, int warpM, int warpN,
    GemmOut& o)
{
#pragma unroll
    for (int mt = 0; mt < 2; mt++)
#pragma unroll
        for (int nt = 0; nt < 8; nt++)
#pragma unroll
            for (int j = 0; j < 4; j++) o.d[mt][nt][j] = 0.f;

    const unsigned aOff =
        ((unsigned)((warpM * 32 + (lane & 15)) * G_STR + (lane >> 4) * 8)) * 2u;
    const unsigned bOff = G_TILE_B +
        ((unsigned)((warpN * 64 + (lane & 7) + ((lane >> 4) & 1) * 8) * G_STR
                    + ((lane >> 3) & 1) * 8)) * 2u;

    gemm_stage(A, Bt, s0,             rowBase, colBase, 0,  tid); CP_COMMIT;
    gemm_stage(A, Bt, s0 + G_STAGE_B, rowBase, colBase, 64, tid); CP_COMMIT;

    for (int itn = 0; itn < 16; itn++) {
        const unsigned stg = s0 + (unsigned)(itn % 3) * G_STAGE_B;
        if (itn >= 14) { CP_WAIT0; } else { CP_WAIT1; }
        __syncthreads();
        if (itn + 2 < 16) {
            gemm_stage(A, Bt, s0 + (unsigned)((itn + 2) % 3) * G_STAGE_B,
                       rowBase, colBase, (itn + 2) * 64, tid);
            CP_COMMIT;
        }
        const unsigned aB = stg + aOff;
        const unsigned bB = stg + bOff;

#pragma unroll
        for (int kk = 0; kk < 4; kk++) {
            unsigned a0[4], a1[4];
            ldsm4(a0[0], a0[1], a0[2], a0[3], aB + kk * 32);
            ldsm4(a1[0], a1[1], a1[2], a1[3], aB + 16 * G_STR * 2 + kk * 32);
#pragma unroll
            for (int p = 0; p < 4; p++) {
                unsigned r0, r1, r2, r3;
                ldsm4(r0, r1, r2, r3, bB + p * 16 * G_STR * 2 + kk * 32);
                mma_fp16(o.d[0][2 * p],     a0, r0, r1);
                mma_fp16(o.d[0][2 * p + 1], a0, r2, r3);
                mma_fp16(o.d[1][2 * p],     a1, r0, r1);
                mma_fp16(o.d[1][2 * p + 1], a1, r2, r3);
            }
        }
    }
}

// QKV GEMM: grid.z selects q/k/v; scatter fp16 to [b,h,s,hd]
__global__ __launch_bounds__(256, 2) void gemm_qkv(
    const __half* __restrict__ A, const __half* __restrict__ WtBase,
    const float* __restrict__ bq, const float* __restrict__ bk,
    const float* __restrict__ bv, __half* __restrict__ Obase)
{
    extern __shared__ __half gsm[];
    const unsigned s0 = saddr(gsm);

    const int z = blockIdx.z;
    const __half* Bt = WtBase + (size_t)z * DM * DM;
    const float* bias = (z == 0) ? bq : (z == 1) ? bk : bv;
    __half* C = Obase + (size_t)z * (BATCH * NH * SEQ * HD);
    // Q scale folds 1/sqrt(64) AND log2(e) for exp2-softmax
    const float scale = (z == 0) ? 0.125f * 1.4426950408889634f : 1.0f;

    const int tid   = threadIdx.x;
    const int lane  = tid & 31;
    const int warp  = tid >> 5;
    const int warpM = warp & 3;
    const int warpN = warp >> 2;
    const int g     = lane >> 2;
    const int t     = lane & 3;
    const int rowBase = blockIdx.y * 128;
    const int colBase = blockIdx.x * 128;

    GemmOut o;
    gemm_core(A, Bt, s0, rowBase, colBase, tid, lane, warpM, warpN, o);

#pragma unroll
    for (int mt = 0; mt < 2; mt++) {
        int row0 = rowBase + warpM * 32 + mt * 16 + g;
#pragma unroll
        for (int nt = 0; nt < 8; nt++) {
            int col = colBase + warpN * 64 + nt * 8 + 2 * t;
            float bb0 = bias[col], bb1 = bias[col + 1];
            unsigned v0 = h2pack((o.d[mt][nt][0] + bb0) * scale,
                                 (o.d[mt][nt][1] + bb1) * scale);
            unsigned v1 = h2pack((o.d[mt][nt][2] + bb0) * scale,
                                 (o.d[mt][nt][3] + bb1) * scale);
            int h = col >> 6, hd = col & 63;
            int b0i = row0 >> 11, s0i = row0 & 2047;
            int r1 = row0 + 8;
            int b1i = r1 >> 11, s1i = r1 & 2047;
            *(unsigned*)(C + (((size_t)(b0i * NH + h) * SEQ) + s0i) * HD + hd) = v0;
            *(unsigned*)(C + (((size_t)(b1i * NH + h) * SEQ) + s1i) * HD + hd) = v1;
        }
    }
}

// Output GEMM: fp32 plain row-major out
__global__ __launch_bounds__(256, 2) void gemm_out(
    const __half* __restrict__ A, const __half* __restrict__ Bt,
    const float* __restrict__ bias, float* __restrict__ C)
{
    extern __shared__ __half gsm[];
    const unsigned s0 = saddr(gsm);

    const int tid   = threadIdx.x;
    const int lane  = tid & 31;
    const int warp  = tid >> 5;
    const int warpM = warp & 3;
    const int warpN = warp >> 2;
    const int g     = lane >> 2;
    const int t     = lane & 3;
    const int rowBase = blockIdx.y * 128;
    const int colBase = blockIdx.x * 128;

    GemmOut o;
    gemm_core(A, Bt, s0, rowBase, colBase, tid, lane, warpM, warpN, o);

#pragma unroll
    for (int mt = 0; mt < 2; mt++) {
        int row0 = rowBase + warpM * 32 + mt * 16 + g;
#pragma unroll
        for (int nt = 0; nt < 8; nt++) {
            int col = colBase + warpN * 64 + nt * 8 + 2 * t;
            float bb0 = bias[col], bb1 = bias[col + 1];
            *(float2*)(C + (size_t)row0 * DM + col) =
                make_float2(o.d[mt][nt][0] + bb0, o.d[mt][nt][1] + bb1);
            *(float2*)(C + (size_t)(row0 + 8) * DM + col) =
                make_float2(o.d[mt][nt][2] + bb0, o.d[mt][nt][3] + bb1);
        }
    }
}

// ---------------------------------------------------------------------------
// Flash attention fp16: 64q x 64k tiles, 128 threads, 4 CTAs/SM.
// Q pre-scaled by 0.125*log2(e); softmax in base-2 (exp2f).
// smem: Qs[64][72h] | Ks[2][64][72h] | Vs[2][64][72h] = 46080 B
// ---------------------------------------------------------------------------
#define F_STR 72
#define FQ_B (64 * F_STR * 2)      // 9216
#define FK_B (64 * F_STR * 2)      // 9216
#define FA_SMEM (FQ_B + 4 * FK_B)  // 46080

__device__ __forceinline__ void fa_stage(
    const __half* __restrict__ Kb, const __half* __restrict__ Vb,
    unsigned Kd, unsigned Vd, int tid)
{
#pragma unroll
    for (int it = 0; it < 4; it++) {
        int idx = tid + it * 128;       // 0..511
        int r   = idx >> 3;             // 0..63
        int c8  = (idx & 7) * 8;
        cp16(Kd + (unsigned)(r * F_STR + c8) * 2, Kb + r * HD + c8);
        cp16(Vd + (unsigned)(r * F_STR + c8) * 2, Vb + r * HD + c8);
    }
}

__global__ __launch_bounds__(128, 4) void flash_fp16(
    const __half* __restrict__ Q, const __half* __restrict__ K,
    const __half* __restrict__ V, __half* __restrict__ ctx)
{
    extern __shared__ __half fsm[];
    const unsigned sQ = saddr(fsm);
    const unsigned sK = sQ + FQ_B;
    const unsigned sV = sK + 2 * FK_B;

    const int tid  = threadIdx.x;
    const int lane = tid & 31;
    const int warp = tid >> 5;      // 0..3
    const int g    = lane >> 2;
    const int t    = lane & 3;
    const int qt   = blockIdx.x;
    const int bh   = blockIdx.y;
    const int Q0   = qt * 64;
    const int rb   = warp * 16;

    const size_t base = (size_t)bh * SEQ * HD;

    const unsigned qAddr = sQ +
        ((unsigned)((rb + (lane & 15)) * F_STR + (lane >> 4) * 8)) * 2u;
    const unsigned kOff =
        ((unsigned)(((lane & 7) + ((lane >> 4) & 1) * 8) * F_STR
                    + ((lane >> 3) & 1) * 8)) * 2u;
    const unsigned vOff =
        ((unsigned)(((lane & 7) + ((lane >> 3) & 1) * 8) * F_STR
                    + (lane >> 4) * 8)) * 2u;

    // prologue: stage Q + K/V tile 0
    {
        const __half* Qb = Q + base + (size_t)Q0 * HD;
#pragma unroll
        for (int it = 0; it < 4; it++) {
            int idx = tid + it * 128;   // 0..511
            int r   = idx >> 3;         // 0..63
            int c8  = (idx & 7) * 8;
            cp16(sQ + (unsigned)(r * F_STR + c8) * 2, Qb + r * HD + c8);
        }
        fa_stage(K + base, V + base, sK, sV, tid);
        CP_COMMIT;
    }

    float m[2] = {-INFINITY, -INFINITY};
    float l[2] = {0.f, 0.f};
    float O[8][4];
#pragma unroll
    for (int nf = 0; nf < 8; nf++)
#pragma unroll
        for (int j = 0; j < 4; j++) O[nf][j] = 0.f;

    int buf = 0;
    for (int kt = 0; kt <= qt; kt++) {
        CP_WAIT0;
        __syncthreads();
        if (kt < qt) {
            fa_stage(K + base + (size_t)(kt + 1) * 64 * HD,
                     V + base + (size_t)(kt + 1) * 64 * HD,
                     sK + (buf ^ 1) * FK_B, sV + (buf ^ 1) * FK_B, tid);
            CP_COMMIT;
        }
        const unsigned kB = sK + buf * FK_B + kOff;
        const unsigned vB = sV + buf * FK_B + vOff;

        // S = Q K^T
        float S[8][4];
#pragma unroll
        for (int nf = 0; nf < 8; nf++)
#pragma unroll
            for (int j = 0; j < 4; j++) S[nf][j] = 0.f;

#pragma unroll
        for (int kk = 0; kk < 4; kk++) {
            unsigned a[4];
            ldsm4(a[0], a[1], a[2], a[3], qAddr + kk * 32);
#pragma unroll
            for (int p = 0; p < 4; p++) {
                unsigned r0, r1, r2, r3;
                ldsm4(r0, r1, r2, r3, kB + p * 16 * F_STR * 2 + kk * 32);
                mma_fp16(S[2 * p],     a, r0, r1);
                mma_fp16(S[2 * p + 1], a, r2, r3);
            }
        }

        if (kt == qt) {   // diagonal tile causal mask
            int kb = kt * 64;
            int rlo = Q0 + rb + g, rhi = rlo + 8;
#pragma unroll
            for (int nf = 0; nf < 8; nf++) {
                int k0 = kb + nf * 8 + 2 * t;
                if (k0     > rlo) S[nf][0] = -INFINITY;
                if (k0 + 1 > rlo) S[nf][1] = -INFINITY;
                if (k0     > rhi) S[nf][2] = -INFINITY;
                if (k0 + 1 > rhi) S[nf][3] = -INFINITY;
            }
        }

        // online softmax (base-2)
#pragma unroll
        for (int h2 = 0; h2 < 2; h2++) {
            float mx = -INFINITY;
#pragma unroll
            for (int nf = 0; nf < 8; nf++)
                mx = fmaxf(mx, fmaxf(S[nf][2 * h2], S[nf][2 * h2 + 1]));
            mx = fmaxf(mx, __shfl_xor_sync(0xffffffffu, mx, 1));
            mx = fmaxf(mx, __shfl_xor_sync(0xffffffffu, mx, 2));
            float mn = fmaxf(m[h2], mx);
            float sc = exp2f(m[h2] - mn);
            m[h2] = mn;
            float rs = 0.f;
#pragma unroll
            for (int nf = 0; nf < 8; nf++) {
                float e0 = exp2f(S[nf][2 * h2]     - mn);
                float e1 = exp2f(S[nf][2 * h2 + 1] - mn);
                S[nf][2 * h2] = e0; S[nf][2 * h2 + 1] = e1;
                rs += e0 + e1;
            }
            rs += __shfl_xor_sync(0xffffffffu, rs, 1);
            rs += __shfl_xor_sync(0xffffffffu, rs, 2);
            l[h2] = l[h2] * sc + rs;
#pragma unroll
            for (int nf = 0; nf < 8; nf++) {
                O[nf][2 * h2]     *= sc;
                O[nf][2 * h2 + 1] *= sc;
            }
        }

        // O += P V  (P packs directly into fp16 A-frags)
#pragma unroll
        for (int mkey = 0; mkey < 4; mkey++) {
            unsigned a[4];
            a[0] = h2pack(S[2 * mkey][0],     S[2 * mkey][1]);
            a[1] = h2pack(S[2 * mkey][2],     S[2 * mkey][3]);
            a[2] = h2pack(S[2 * mkey + 1][0], S[2 * mkey + 1][1]);
            a[3] = h2pack(S[2 * mkey + 1][2], S[2 * mkey + 1][3]);
#pragma unroll
            for (int p = 0; p < 4; p++) {
                unsigned r0, r1, r2, r3;
                ldsm4t(r0, r1, r2, r3,
                       vB + (mkey * 16 * F_STR + p * 16) * 2);
                mma_fp16(O[2 * p],     a, r0, r1);
                mma_fp16(O[2 * p + 1], a, r2, r3);
            }
        }
        buf ^= 1;
    }

    // epilogue
    const int b = bh >> 4, hh = bh & 15;
#pragma unroll
    for (int h2 = 0; h2 < 2; h2++) {
        float inv = 1.f / l[h2];
        int row = Q0 + rb + g + 8 * h2;
        __half* dst = ctx + ((size_t)(b * SEQ + row)) * DM + hh * HD;
#pragma unroll
        for (int nf = 0; nf < 8; nf++) {
            int c = nf * 8 + 2 * t;
            *(unsigned*)(dst + c) =
                h2pack(O[nf][2 * h2] * inv, O[nf][2 * h2 + 1] * inv);
        }
    }
}

// ---------------------------------------------------------------------------
// Launch
// ---------------------------------------------------------------------------
extern "C" void kernel_launch(void* const* d_in, const int* in_sizes, int n_in,
                              void* d_out, int out_size)
{
    const float* x  = (const float*)d_in[0];
    const float* wq = (const float*)d_in[1];
    const float* bq = (const float*)d_in[2];
    const float* wk = (const float*)d_in[3];
    const float* bk = (const float*)d_in[4];
    const float* wv = (const float*)d_in[5];
    const float* bv = (const float*)d_in[6];
    const float* wo = (const float*)d_in[7];
    const float* bo = (const float*)d_in[8];
    float* out = (float*)d_out;

    __half *qkv, *ctx, *xh, *wth;
    cudaGetSymbolAddress((void**)&qkv, g_qkv);
    cudaGetSymbolAddress((void**)&ctx, g_ctx);
    cudaGetSymbolAddress((void**)&xh,  g_xh);
    cudaGetSymbolAddress((void**)&wth, g_wth);
    const size_t HSZ = (size_t)BATCH * NH * SEQ * HD;

    cudaFuncSetAttribute(gemm_qkv,
                         cudaFuncAttributeMaxDynamicSharedMemorySize, G_SMEM);
    cudaFuncSetAttribute(gemm_out,
                         cudaFuncAttributeMaxDynamicSharedMemorySize, G_SMEM);
    cudaFuncSetAttribute(flash_fp16,
                         cudaFuncAttributeMaxDynamicSharedMemorySize, FA_SMEM);

    // preprocess
    {
        int n4x = MROWS * DM / 4;
        round_fp16_k<<<(n4x + 255) / 256, 256>>>(x, xh, n4x);
        transpose_fp16_k<<<dim3(32, 32, 4), dim3(32, 8)>>>(wq, wk, wv, wo, wth);
    }

    gemm_qkv<<<dim3(DM / 128, MROWS / 128, 3), 256, G_SMEM>>>(
        xh, wth, bq, bk, bv, qkv);

    flash_fp16<<<dim3(SEQ / 64, BATCH * NH), 128, FA_SMEM>>>(
        qkv, qkv + HSZ, qkv + 2 * HSZ, ctx);

    gemm_out<<<dim3(DM / 128, MROWS / 128), 256, G_SMEM>>>(
        ctx, wth + 3 * (size_t)DM * DM, bo, out);
}

// round 12
// speedup vs baseline: 7.5601x; 1.0302x over previous
#include <cuda_runtime.h>
#include <cuda_fp16.h>
#include <math.h>

#define BATCH 4
#define SEQ   2048
#define DM    1024
#define NH    16
#define HD    64
#define MROWS (BATCH * SEQ)   // 8192

__device__ __half g_qkv[3][BATCH * NH * SEQ * HD];
__device__ __half g_ctx[MROWS * DM];
__device__ __half g_xh[MROWS * DM];
__device__ __half g_wth[4][DM * DM];       // fp16 TRANSPOSED weights [out][in]

// ---------------------------------------------------------------------------
// helpers
// ---------------------------------------------------------------------------
__device__ __forceinline__ unsigned h2pack(float a, float b) {
    __half2 h = __floats2half2_rn(a, b);
    return *(unsigned*)&h;
}

__device__ __forceinline__ void mma_fp16(float* d, const unsigned* a,
                                         unsigned b0, unsigned b1) {
    asm volatile(
        "mma.sync.aligned.m16n8k16.row.col.f32.f16.f16.f32 "
        "{%0,%1,%2,%3}, {%4,%5,%6,%7}, {%8,%9}, {%0,%1,%2,%3};\n"
        : "+f"(d[0]), "+f"(d[1]), "+f"(d[2]), "+f"(d[3])
        : "r"(a[0]), "r"(a[1]), "r"(a[2]), "r"(a[3]), "r"(b0), "r"(b1));
}

__device__ __forceinline__ unsigned ex2_f16x2(unsigned x) {
    unsigned r;
    asm("ex2.approx.f16x2 %0, %1;" : "=r"(r) : "r"(x));
    return r;
}

__device__ __forceinline__ unsigned saddr(const void* p) {
    return (unsigned)__cvta_generic_to_shared(p);
}
__device__ __forceinline__ void cp16(unsigned d, const void* s) {
    asm volatile("cp.async.cg.shared.global [%0], [%1], 16;" :: "r"(d), "l"(s));
}
#define CP_COMMIT asm volatile("cp.async.commit_group;")
#define CP_WAIT0  asm volatile("cp.async.wait_group 0;")
#define CP_WAIT1  asm volatile("cp.async.wait_group 1;")

__device__ __forceinline__ void ldsm4(unsigned& r0, unsigned& r1,
                                      unsigned& r2, unsigned& r3, unsigned a) {
    asm volatile("ldmatrix.sync.aligned.m8n8.x4.shared.b16 {%0,%1,%2,%3}, [%4];"
                 : "=r"(r0), "=r"(r1), "=r"(r2), "=r"(r3) : "r"(a));
}
__device__ __forceinline__ void ldsm4t(unsigned& r0, unsigned& r1,
                                       unsigned& r2, unsigned& r3, unsigned a) {
    asm volatile("ldmatrix.sync.aligned.m8n8.x4.trans.shared.b16 {%0,%1,%2,%3}, [%4];"
                 : "=r"(r0), "=r"(r1), "=r"(r2), "=r"(r3) : "r"(a));
}

// ---------------------------------------------------------------------------
// preprocessing
// ---------------------------------------------------------------------------
__global__ void round_fp16_k(const float* __restrict__ in,
                             __half* __restrict__ out, int n4)
{
    int i = blockIdx.x * blockDim.x + threadIdx.x;
    if (i < n4) {
        float4 v = ((const float4*)in)[i];
        __half2* o = (__half2*)(out + i * 4);
        o[0] = __floats2half2_rn(v.x, v.y);
        o[1] = __floats2half2_rn(v.z, v.w);
    }
}

__global__ void transpose_fp16_k(const float* __restrict__ w0,
                                 const float* __restrict__ w1,
                                 const float* __restrict__ w2,
                                 const float* __restrict__ w3,
                                 __half* __restrict__ out)
{
    __shared__ float t[32][33];
    const float* in = (blockIdx.z == 0) ? w0 : (blockIdx.z == 1) ? w1
                    : (blockIdx.z == 2) ? w2 : w3;
    __half* o = out + (size_t)blockIdx.z * DM * DM;
    int bx = blockIdx.x * 32, by = blockIdx.y * 32;
    int tx = threadIdx.x;
#pragma unroll
    for (int i = threadIdx.y; i < 32; i += 8)
        t[i][tx] = in[(size_t)(by + i) * DM + bx + tx];
    __syncthreads();
#pragma unroll
    for (int i = threadIdx.y; i < 32; i += 8)
        o[(size_t)(bx + i) * DM + by + tx] = __float2half_rn(t[tx][i]);
}

// ---------------------------------------------------------------------------
// fp16 GEMM core, 3-stage cp.async ring (unchanged from R10)
// ---------------------------------------------------------------------------
#define G_STR 72
#define G_TILE_B (128 * G_STR * 2)
#define G_STAGE_B (2 * G_TILE_B)
#define G_SMEM (3 * G_STAGE_B)

__device__ __forceinline__ void gemm_stage(
    const __half* __restrict__ A, const __half* __restrict__ Bt,
    unsigned stageBase, int rowBase, int colBase, int k0, int tid)
{
    unsigned Ab = stageBase;
    unsigned Bb = stageBase + G_TILE_B;
#pragma unroll
    for (int it = 0; it < 4; it++) {
        int idx = tid + it * 256;
        int r   = idx >> 3;
        int c8  = (idx & 7) * 8;
        cp16(Ab + (unsigned)(r * G_STR + c8) * 2,
             A  + (size_t)(rowBase + r) * DM + k0 + c8);
        cp16(Bb + (unsigned)(r * G_STR + c8) * 2,
             Bt + (size_t)(colBase + r) * DM + k0 + c8);
    }
}

struct GemmOut {
    float d[2][8][4];
};

__device__ __forceinline__ void gemm_core(
    const __half* A, const __half* Bt, unsigned s0,
    int rowBase, int colBase, int tid, int lane, int warpM, int warpN,
    GemmOut& o)
{
#pragma unroll
    for (int mt = 0; mt < 2; mt++)
#pragma unroll
        for (int nt = 0; nt < 8; nt++)
#pragma unroll
            for (int j = 0; j < 4; j++) o.d[mt][nt][j] = 0.f;

    const unsigned aOff =
        ((unsigned)((warpM * 32 + (lane & 15)) * G_STR + (lane >> 4) * 8)) * 2u;
    const unsigned bOff = G_TILE_B +
        ((unsigned)((warpN * 64 + (lane & 7) + ((lane >> 4) & 1) * 8) * G_STR
                    + ((lane >> 3) & 1) * 8)) * 2u;

    gemm_stage(A, Bt, s0,             rowBase, colBase, 0,  tid); CP_COMMIT;
    gemm_stage(A, Bt, s0 + G_STAGE_B, rowBase, colBase, 64, tid); CP_COMMIT;

    for (int itn = 0; itn < 16; itn++) {
        const unsigned stg = s0 + (unsigned)(itn % 3) * G_STAGE_B;
        if (itn >= 14) { CP_WAIT0; } else { CP_WAIT1; }
        __syncthreads();
        if (itn + 2 < 16) {
            gemm_stage(A, Bt, s0 + (unsigned)((itn + 2) % 3) * G_STAGE_B,
                       rowBase, colBase, (itn + 2) * 64, tid);
            CP_COMMIT;
        }
        const unsigned aB = stg + aOff;
        const unsigned bB = stg + bOff;

#pragma unroll
        for (int kk = 0; kk < 4; kk++) {
            unsigned a0[4], a1[4];
            ldsm4(a0[0], a0[1], a0[2], a0[3], aB + kk * 32);
            ldsm4(a1[0], a1[1], a1[2], a1[3], aB + 16 * G_STR * 2 + kk * 32);
#pragma unroll
            for (int p = 0; p < 4; p++) {
                unsigned r0, r1, r2, r3;
                ldsm4(r0, r1, r2, r3, bB + p * 16 * G_STR * 2 + kk * 32);
                mma_fp16(o.d[0][2 * p],     a0, r0, r1);
                mma_fp16(o.d[0][2 * p + 1], a0, r2, r3);
                mma_fp16(o.d[1][2 * p],     a1, r0, r1);
                mma_fp16(o.d[1][2 * p + 1], a1, r2, r3);
            }
        }
    }
}

__global__ __launch_bounds__(256, 2) void gemm_qkv(
    const __half* __restrict__ A, const __half* __restrict__ WtBase,
    const float* __restrict__ bq, const float* __restrict__ bk,
    const float* __restrict__ bv, __half* __restrict__ Obase)
{
    extern __shared__ __half gsm[];
    const unsigned s0 = saddr(gsm);

    const int z = blockIdx.z;
    const __half* Bt = WtBase + (size_t)z * DM * DM;
    const float* bias = (z == 0) ? bq : (z == 1) ? bk : bv;
    __half* C = Obase + (size_t)z * (BATCH * NH * SEQ * HD);
    const float scale = (z == 0) ? 0.125f * 1.4426950408889634f : 1.0f;

    const int tid   = threadIdx.x;
    const int lane  = tid & 31;
    const int warp  = tid >> 5;
    const int warpM = warp & 3;
    const int warpN = warp >> 2;
    const int g     = lane >> 2;
    const int t     = lane & 3;
    const int rowBase = blockIdx.y * 128;
    const int colBase = blockIdx.x * 128;

    GemmOut o;
    gemm_core(A, Bt, s0, rowBase, colBase, tid, lane, warpM, warpN, o);

#pragma unroll
    for (int mt = 0; mt < 2; mt++) {
        int row0 = rowBase + warpM * 32 + mt * 16 + g;
#pragma unroll
        for (int nt = 0; nt < 8; nt++) {
            int col = colBase + warpN * 64 + nt * 8 + 2 * t;
            float bb0 = bias[col], bb1 = bias[col + 1];
            unsigned v0 = h2pack((o.d[mt][nt][0] + bb0) * scale,
                                 (o.d[mt][nt][1] + bb1) * scale);
            unsigned v1 = h2pack((o.d[mt][nt][2] + bb0) * scale,
                                 (o.d[mt][nt][3] + bb1) * scale);
            int h = col >> 6, hd = col & 63;
            int b0i = row0 >> 11, s0i = row0 & 2047;
            int r1 = row0 + 8;
            int b1i = r1 >> 11, s1i = r1 & 2047;
            *(unsigned*)(C + (((size_t)(b0i * NH + h) * SEQ) + s0i) * HD + hd) = v0;
            *(unsigned*)(C + (((size_t)(b1i * NH + h) * SEQ) + s1i) * HD + hd) = v1;
        }
    }
}

__global__ __launch_bounds__(256, 2) void gemm_out(
    const __half* __restrict__ A, const __half* __restrict__ Bt,
    const float* __restrict__ bias, float* __restrict__ C)
{
    extern __shared__ __half gsm[];
    const unsigned s0 = saddr(gsm);

    const int tid   = threadIdx.x;
    const int lane  = tid & 31;
    const int warp  = tid >> 5;
    const int warpM = warp & 3;
    const int warpN = warp >> 2;
    const int g     = lane >> 2;
    const int t     = lane & 3;
    const int rowBase = blockIdx.y * 128;
    const int colBase = blockIdx.x * 128;

    GemmOut o;
    gemm_core(A, Bt, s0, rowBase, colBase, tid, lane, warpM, warpN, o);

#pragma unroll
    for (int mt = 0; mt < 2; mt++) {
        int row0 = rowBase + warpM * 32 + mt * 16 + g;
#pragma unroll
        for (int nt = 0; nt < 8; nt++) {
            int col = colBase + warpN * 64 + nt * 8 + 2 * t;
            float bb0 = bias[col], bb1 = bias[col + 1];
            *(float2*)(C + (size_t)row0 * DM + col) =
                make_float2(o.d[mt][nt][0] + bb0, o.d[mt][nt][1] + bb1);
            *(float2*)(C + (size_t)(row0 + 8) * DM + col) =
                make_float2(o.d[mt][nt][2] + bb0, o.d[mt][nt][3] + bb1);
        }
    }
}

// ---------------------------------------------------------------------------
// Flash attention fp16: 64q x 64k, 128 threads, 4 CTAs/SM.
// Base-2 softmax with ex2.approx.f16x2; row-sum l via all-ones MMA column.
// ---------------------------------------------------------------------------
#define F_STR 72
#define FQ_B (64 * F_STR * 2)
#define FK_B (64 * F_STR * 2)
#define FA_SMEM (FQ_B + 4 * FK_B)  // 46080

#define ONES_H2 0x3C003C00u        // (1.0h, 1.0h)

__device__ __forceinline__ void fa_stage(
    const __half* __restrict__ Kb, const __half* __restrict__ Vb,
    unsigned Kd, unsigned Vd, int tid)
{
#pragma unroll
    for (int it = 0; it < 4; it++) {
        int idx = tid + it * 128;
        int r   = idx >> 3;
        int c8  = (idx & 7) * 8;
        cp16(Kd + (unsigned)(r * F_STR + c8) * 2, Kb + r * HD + c8);
        cp16(Vd + (unsigned)(r * F_STR + c8) * 2, Vb + r * HD + c8);
    }
}

__global__ __launch_bounds__(128, 4) void flash_fp16(
    const __half* __restrict__ Q, const __half* __restrict__ K,
    const __half* __restrict__ V, __half* __restrict__ ctx)
{
    extern __shared__ __half fsm[];
    const unsigned sQ = saddr(fsm);
    const unsigned sK = sQ + FQ_B;
    const unsigned sV = sK + 2 * FK_B;

    const int tid  = threadIdx.x;
    const int lane = tid & 31;
    const int warp = tid >> 5;
    const int g    = lane >> 2;
    const int t    = lane & 3;
    const int qt   = blockIdx.x;
    const int bh   = blockIdx.y;
    const int Q0   = qt * 64;
    const int rb   = warp * 16;

    const size_t base = (size_t)bh * SEQ * HD;

    const unsigned qAddr = sQ +
        ((unsigned)((rb + (lane & 15)) * F_STR + (lane >> 4) * 8)) * 2u;
    const unsigned kOff =
        ((unsigned)(((lane & 7) + ((lane >> 4) & 1) * 8) * F_STR
                    + ((lane >> 3) & 1) * 8)) * 2u;
    const unsigned vOff =
        ((unsigned)(((lane & 7) + ((lane >> 3) & 1) * 8) * F_STR
                    + (lane >> 4) * 8)) * 2u;

    // prologue
    {
        const __half* Qb = Q + base + (size_t)Q0 * HD;
#pragma unroll
        for (int it = 0; it < 4; it++) {
            int idx = tid + it * 128;
            int r   = idx >> 3;
            int c8  = (idx & 7) * 8;
            cp16(sQ + (unsigned)(r * F_STR + c8) * 2, Qb + r * HD + c8);
        }
        fa_stage(K + base, V + base, sK, sV, tid);
        CP_COMMIT;
    }

    float m[2] = {-INFINITY, -INFINITY};
    float O[9][4];                       // frag 8 = row-sum column (l)
#pragma unroll
    for (int nf = 0; nf < 9; nf++)
#pragma unroll
        for (int j = 0; j < 4; j++) O[nf][j] = 0.f;

    int buf = 0;
    for (int kt = 0; kt <= qt; kt++) {
        CP_WAIT0;
        __syncthreads();
        if (kt < qt) {
            fa_stage(K + base + (size_t)(kt + 1) * 64 * HD,
                     V + base + (size_t)(kt + 1) * 64 * HD,
                     sK + (buf ^ 1) * FK_B, sV + (buf ^ 1) * FK_B, tid);
            CP_COMMIT;
        }
        const unsigned kB = sK + buf * FK_B + kOff;
        const unsigned vB = sV + buf * FK_B + vOff;

        // S = Q K^T (fp32 accum)
        float S[8][4];
#pragma unroll
        for (int nf = 0; nf < 8; nf++)
#pragma unroll
            for (int j = 0; j < 4; j++) S[nf][j] = 0.f;

#pragma unroll
        for (int kk = 0; kk < 4; kk++) {
            unsigned a[4];
            ldsm4(a[0], a[1], a[2], a[3], qAddr + kk * 32);
#pragma unroll
            for (int p = 0; p < 4; p++) {
                unsigned r0, r1, r2, r3;
                ldsm4(r0, r1, r2, r3, kB + p * 16 * F_STR * 2 + kk * 32);
                mma_fp16(S[2 * p],     a, r0, r1);
                mma_fp16(S[2 * p + 1], a, r2, r3);
            }
        }

        if (kt == qt) {   // diagonal tile causal mask
            int kb = kt * 64;
            int rlo = Q0 + rb + g, rhi = rlo + 8;
#pragma unroll
            for (int nf = 0; nf < 8; nf++) {
                int k0 = kb + nf * 8 + 2 * t;
                if (k0     > rlo) S[nf][0] = -INFINITY;
                if (k0 + 1 > rlo) S[nf][1] = -INFINITY;
                if (k0     > rhi) S[nf][2] = -INFINITY;
                if (k0 + 1 > rhi) S[nf][3] = -INFINITY;
            }
        }

        // online softmax (base-2), fp16x2 exponent path
        float sc0, sc1;
        {
            float mx0 = -INFINITY, mx1 = -INFINITY;
#pragma unroll
            for (int nf = 0; nf < 8; nf++) {
                mx0 = fmaxf(mx0, fmaxf(S[nf][0], S[nf][1]));
                mx1 = fmaxf(mx1, fmaxf(S[nf][2], S[nf][3]));
            }
            mx0 = fmaxf(mx0, __shfl_xor_sync(0xffffffffu, mx0, 1));
            mx0 = fmaxf(mx0, __shfl_xor_sync(0xffffffffu, mx0, 2));
            mx1 = fmaxf(mx1, __shfl_xor_sync(0xffffffffu, mx1, 1));
            mx1 = fmaxf(mx1, __shfl_xor_sync(0xffffffffu, mx1, 2));
            float mn0 = fmaxf(m[0], mx0);
            float mn1 = fmaxf(m[1], mx1);
            sc0 = exp2f(m[0] - mn0);
            sc1 = exp2f(m[1] - mn1);
            m[0] = mn0; m[1] = mn1;
        }

        // P = exp2(S - m) directly in fp16x2 (A-frag layout)
        unsigned E[8][2];
        {
            __half2 hm0 = __float2half2_rn(m[0]);
            __half2 hm1 = __float2half2_rn(m[1]);
#pragma unroll
            for (int nf = 0; nf < 8; nf++) {
                __half2 p0 = __floats2half2_rn(S[nf][0], S[nf][1]);
                __half2 p1 = __floats2half2_rn(S[nf][2], S[nf][3]);
                p0 = __hsub2(p0, hm0);
                p1 = __hsub2(p1, hm1);
                E[nf][0] = ex2_f16x2(*(unsigned*)&p0);
                E[nf][1] = ex2_f16x2(*(unsigned*)&p1);
            }
        }

        // rescale O (including the l column)
#pragma unroll
        for (int nf = 0; nf < 9; nf++) {
            O[nf][0] *= sc0; O[nf][1] *= sc0;
            O[nf][2] *= sc1; O[nf][3] *= sc1;
        }

        // O += P V ; l column += P @ 1
#pragma unroll
        for (int mkey = 0; mkey < 4; mkey++) {
            unsigned a[4];
            a[0] = E[2 * mkey][0];
            a[1] = E[2 * mkey][1];
            a[2] = E[2 * mkey + 1][0];
            a[3] = E[2 * mkey + 1][1];
#pragma unroll
            for (int p = 0; p < 4; p++) {
                unsigned r0, r1, r2, r3;
                ldsm4t(r0, r1, r2, r3,
                       vB + (mkey * 16 * F_STR + p * 16) * 2);
                mma_fp16(O[2 * p],     a, r0, r1);
                mma_fp16(O[2 * p + 1], a, r2, r3);
            }
            mma_fp16(O[8], a, ONES_H2, ONES_H2);
        }
        buf ^= 1;
    }

    // epilogue: l lives in O[8] (same value in all 4 quad lanes' cols)
    const int b = bh >> 4, hh = bh & 15;
    const float inv0 = 1.f / O[8][0];
    const float inv1 = 1.f / O[8][2];
#pragma unroll
    for (int h2 = 0; h2 < 2; h2++) {
        float inv = h2 ? inv1 : inv0;
        int row = Q0 + rb + g + 8 * h2;
        __half* dst = ctx + ((size_t)(b * SEQ + row)) * DM + hh * HD;
#pragma unroll
        for (int nf = 0; nf < 8; nf++) {
            int c = nf * 8 + 2 * t;
            *(unsigned*)(dst + c) =
                h2pack(O[nf][2 * h2] * inv, O[nf][2 * h2 + 1] * inv);
        }
    }
}

// ---------------------------------------------------------------------------
// Launch
// ---------------------------------------------------------------------------
extern "C" void kernel_launch(void* const* d_in, const int* in_sizes, int n_in,
                              void* d_out, int out_size)
{
    const float* x  = (const float*)d_in[0];
    const float* wq = (const float*)d_in[1];
    const float* bq = (const float*)d_in[2];
    const float* wk = (const float*)d_in[3];
    const float* bk = (const float*)d_in[4];
    const float* wv = (const float*)d_in[5];
    const float* bv = (const float*)d_in[6];
    const float* wo = (const float*)d_in[7];
    const float* bo = (const float*)d_in[8];
    float* out = (float*)d_out;

    __half *qkv, *ctx, *xh, *wth;
    cudaGetSymbolAddress((void**)&qkv, g_qkv);
    cudaGetSymbolAddress((void**)&ctx, g_ctx);
    cudaGetSymbolAddress((void**)&xh,  g_xh);
    cudaGetSymbolAddress((void**)&wth, g_wth);
    const size_t HSZ = (size_t)BATCH * NH * SEQ * HD;

    cudaFuncSetAttribute(gemm_qkv,
                         cudaFuncAttributeMaxDynamicSharedMemorySize, G_SMEM);
    cudaFuncSetAttribute(gemm_out,
                         cudaFuncAttributeMaxDynamicSharedMemorySize, G_SMEM);
    cudaFuncSetAttribute(flash_fp16,
                         cudaFuncAttributeMaxDynamicSharedMemorySize, FA_SMEM);

    {
        int n4x = MROWS * DM / 4;
        round_fp16_k<<<(n4x + 255) / 256, 256>>>(x, xh, n4x);
        transpose_fp16_k<<<dim3(32, 32, 4), dim3(32, 8)>>>(wq, wk, wv, wo, wth);
    }

    gemm_qkv<<<dim3(DM / 128, MROWS / 128, 3), 256, G_SMEM>>>(
        xh, wth, bq, bk, bv, qkv);

    flash_fp16<<<dim3(SEQ / 64, BATCH * NH), 128, FA_SMEM>>>(
        qkv, qkv + HSZ, qkv + 2 * HSZ, ctx);

    gemm_out<<<dim3(DM / 128, MROWS / 128), 256, G_SMEM>>>(
        ctx, wth + 3 * (size_t)DM * DM, bo, out);
}